// round 13
// baseline (speedup 1.0000x reference)
#include <cuda_runtime.h>
#include <math.h>
#include <stdint.h>

#define N_NODES 10000
#define N_EDGES 160000
#define N_GRAPHS 64
#define T_TOW 5
#define FI 75
#define FO 15
#define N_LAYERS 4
#define MSG_DIM 375        // T*FI
#define MIN_DIM 225
#define OUT_DIM 975
#define POST_DIM 75
#define PSTRIDE 752        // padded P row: [P1 0..374 | pad | P2 376..750 | pad]
#define P3STRIDE 376
#define HCK 1600
#define HCK2 800
#define HCN 225
#define AVG_DEG_LOG 2.8332133440562162f

// prep1 region sizes
#define NT   (N_LAYERS * MIN_DIM * MSG_DIM)
#define NE   (N_LAYERS * 16 * FI)
#define NB2  (N_LAYERS * FI)
#define NBZ  (N_LAYERS * FI)
#define NPZ  (N_GRAPHS * FI)
#define NCZ  (N_NODES)
#define NH0  (N_NODES * FI)
#define NWB  (N_LAYERS * HCK * HCN)
#define PREP1_TOTAL (NT + NE + NB2 + NBZ + NPZ + NCZ + NH0 + NWB)

// ---------------- scratch (device-side access only) -----------------------------
__device__ float d_h[N_NODES * FI];
__device__ float d_hc[N_NODES * FI];
__device__ float d_P[N_NODES * PSTRIDE];           // pads stay 0
__device__ float d_agg[N_NODES * 1500];
__device__ float d_G0[N_NODES * HCN];
__device__ float d_G1[N_NODES * HCN];
__device__ float d_Wt[N_LAYERS * MIN_DIM * MSG_DIM];
__device__ float d_WB2[N_LAYERS * HCK * HCN];
__device__ float d_P3[N_LAYERS * 16 * P3STRIDE];
__device__ float d_enctab[N_LAYERS * 16 * FI];
__device__ float d_bias2[N_LAYERS * FI];
__device__ int   d_cnt[N_NODES];
__device__ int   d_rowstart[N_NODES + 1];
__device__ int   d_cursor[N_NODES];
__device__ int   d_sc_csr[N_EDGES];                // src*16 + combo
__device__ float d_bnsum[N_LAYERS * FI];
__device__ float d_bnsq[N_LAYERS * FI];
__device__ float d_bnscale[N_LAYERS * FI];
__device__ float d_bnshift[N_LAYERS * FI];
__device__ float d_pool[N_GRAPHS * FI];
__device__ int   d_combine_cnt;

__device__ __forceinline__ float tf32r(float v) {
    uint32_t o;
    asm("cvt.rna.tf32.f32 %0, %1;" : "=r"(o) : "f"(v));
    return __uint_as_float(o);
}

__device__ __forceinline__ void mma_tf32(float* c, const uint32_t* a, const uint32_t* b) {
    asm volatile(
        "mma.sync.aligned.m16n8k8.row.col.f32.tf32.tf32.f32 "
        "{%0,%1,%2,%3}, {%4,%5,%6,%7}, {%8,%9}, {%0,%1,%2,%3};"
        : "+f"(c[0]), "+f"(c[1]), "+f"(c[2]), "+f"(c[3])
        : "r"(a[0]), "r"(a[1]), "r"(a[2]), "r"(a[3]), "r"(b[0]), "r"(b[1]));
}

__device__ __forceinline__ float hval(int l, int n, int f) {
    if (l == 0) return d_h[n * FI + f];
    int o = (l - 1) * FI + f;
    return fmaxf(d_hc[n * FI + f] * d_bnscale[o] + d_bnshift[o], 0.f);
}

// ---------------- prep1: all independent prologue work in one launch ----------------
__global__ void k_prep1(const int* __restrict__ x, const float* __restrict__ node_emb,
                        const float* __restrict__ pre_lin_W, const float* __restrict__ pre_lin_b,
                        const float* __restrict__ preW,
                        const float* __restrict__ edge_emb,
                        const float* __restrict__ encW, const float* __restrict__ encb,
                        const float* __restrict__ postW, const float* __restrict__ linW,
                        const float* __restrict__ postb, const float* __restrict__ linb) {
    int idx = blockIdx.x * blockDim.x + threadIdx.x;
    if (idx < NT) {
        int l = idx / (MIN_DIM * MSG_DIM);
        int r = idx % (MIN_DIM * MSG_DIM);
        int c = r / MSG_DIM, j = r % MSG_DIM;
        int t = j / FI, f = j % FI;
        d_Wt[idx] = preW[((size_t)l * T_TOW + t) * MIN_DIM * FI + c * FI + f];
        return;
    }
    idx -= NT;
    if (idx < NE) {
        int l = idx / (16 * FI);
        int r = idx % (16 * FI);
        int combo = r / FI, f = r % FI;
        int a0 = combo >> 2, a1 = combo & 3;
        const float* e0 = edge_emb + a0 * 25;
        const float* e1 = edge_emb + a1 * 25;
        const float* W = encW + l * 50 * FI;
        float acc = encb[l * FI + f];
        #pragma unroll 5
        for (int q = 0; q < 25; q++) acc += e0[q] * W[q * FI + f];
        #pragma unroll 5
        for (int q = 0; q < 25; q++) acc += e1[q] * W[(25 + q) * FI + f];
        d_enctab[idx] = acc;
        return;
    }
    idx -= NE;
    if (idx < NB2) {
        int l = idx / FI, j = idx % FI;
        const float* lW = linW + l * POST_DIM * FI;
        float acc = linb[l * FI + j];
        #pragma unroll 5
        for (int q = 0; q < POST_DIM; q++) acc += postb[l * POST_DIM + q] * lW[q * FI + j];
        d_bias2[idx] = acc;
        return;
    }
    idx -= NB2;
    if (idx < NBZ) { d_bnsum[idx] = 0.f; d_bnsq[idx] = 0.f; return; }
    idx -= NBZ;
    if (idx < NPZ) { d_pool[idx] = 0.f; return; }
    idx -= NPZ;
    if (idx < NCZ) {
        d_cnt[idx] = 0;
        if (idx == 0) d_combine_cnt = 0;
        return;
    }
    idx -= NCZ;
    if (idx < NH0) {
        int n = idx / FI, f = idx % FI;
        int i0 = x[n * 2 + 0], i1 = x[n * 2 + 1];
        const float* e0 = node_emb + i0 * FI;
        const float* e1 = node_emb + i1 * FI;
        float acc = pre_lin_b[f];
        #pragma unroll 5
        for (int c = 0; c < FI; c++) acc += e0[c] * pre_lin_W[c * FI + f];
        #pragma unroll 5
        for (int c = 0; c < FI; c++) acc += e1[c] * pre_lin_W[(FI + c) * FI + f];
        d_h[idx] = acc;
        return;
    }
    idx -= NH0;
    if (idx < NWB) {
        int l = idx / (HCK * HCN);
        int r = idx % (HCK * HCN);
        int k = r / HCN, j = r % HCN;
        const float* pW = postW + (size_t)l * T_TOW * OUT_DIM * FO;
        const float* lW = linW + l * POST_DIM * FI;
        float acc = 0.f;
        if (k < 1500) {
            int t = k / 300, k300 = k % 300;
            int sel = j / FI, jj = j % FI;
            int c = FI + sel * 300 + k300;
            const float* pw = pW + ((size_t)t * OUT_DIM + c) * FO;
            const float* lw = lW + (t * FO) * FI + jj;
            #pragma unroll
            for (int f = 0; f < FO; f++) acc += pw[f] * lw[f * FI];
        } else if (k < 1575 && j < FI) {
            int c = k - 1500;
            #pragma unroll
            for (int t = 0; t < T_TOW; t++) {
                const float* pw = pW + ((size_t)t * OUT_DIM + c) * FO;
                const float* lw = lW + (t * FO) * FI + j;
                #pragma unroll
                for (int f = 0; f < FO; f++) acc += pw[f] * lw[f * FI];
            }
        }
        d_WB2[idx] = acc;
    }
}

// ---------------- prep2: count + P3 ---------------------------------------------------
__global__ void k_prep2(const int* __restrict__ edge_index) {
    int idx = blockIdx.x * blockDim.x + threadIdx.x;
    if (idx < N_EDGES) {
        atomicAdd(&d_cnt[edge_index[N_EDGES + idx]], 1);
        return;
    }
    idx -= N_EDGES;
    if (idx < N_LAYERS * 16 * P3STRIDE) {
        int l = idx / (16 * P3STRIDE);
        int r = idx % (16 * P3STRIDE);
        int combo = r / P3STRIDE, j = r % P3STRIDE;
        float acc = 0.f;
        if (j < MSG_DIM) {
            const float* e = d_enctab + (l * 16 + combo) * FI;
            const float* W = d_Wt + (size_t)l * MIN_DIM * MSG_DIM;
            #pragma unroll 5
            for (int k = 0; k < FI; k++) acc += e[k] * W[(2 * FI + k) * MSG_DIM + j];
        }
        d_P3[idx] = acc;
    }
}

// ---------------- scan + fill ---------------------------------------------------------
__global__ void k_scan() {
    __shared__ int ssum[1024];
    int tid = threadIdx.x;
    const int ITEMS = 10;
    int base = tid * ITEMS;
    int local[ITEMS];
    int s = 0;
    #pragma unroll
    for (int i = 0; i < ITEMS; i++) {
        int g = base + i;
        int v = (g < N_NODES) ? d_cnt[g] : 0;
        local[i] = s;
        s += v;
    }
    ssum[tid] = s;
    __syncthreads();
    for (int off = 1; off < 1024; off <<= 1) {
        int v = (tid >= off) ? ssum[tid - off] : 0;
        __syncthreads();
        ssum[tid] += v;
        __syncthreads();
    }
    int excl = (tid == 0) ? 0 : ssum[tid - 1];
    #pragma unroll
    for (int i = 0; i < ITEMS; i++) {
        int g = base + i;
        if (g < N_NODES) {
            int rs = excl + local[i];
            d_rowstart[g] = rs;
            d_cursor[g]   = rs;
        }
    }
    if (tid == 0) d_rowstart[N_NODES] = ssum[1023];
}

__global__ void k_fill(const int* __restrict__ edge_index, const int* __restrict__ edge_attr) {
    int e = blockIdx.x * blockDim.x + threadIdx.x;
    if (e >= N_EDGES) return;
    int dst = edge_index[N_EDGES + e];
    int pos = atomicAdd(&d_cursor[dst], 1);
    d_sc_csr[pos] = edge_index[e] * 16 + edge_attr[e * 2] * 4 + edge_attr[e * 2 + 1];
}

// ---------------- P GEMM (BM=128): P[n] = [h|h] @ [W1|W2] + [bias|0] ------------------
__global__ void __launch_bounds__(256, 2) k_gemm_p(int l, const float* __restrict__ bias_all) {
    const int AS = 84, BS = 136;
    __shared__ float As[128 * AS];
    __shared__ float Bs[80 * BS];
    const float* Wt = d_Wt + (size_t)l * MIN_DIM * MSG_DIM;
    const float* bias = bias_all + l * MSG_DIM;
    int tid = threadIdx.x;
    int row0 = blockIdx.y * 128;
    int col0 = blockIdx.x * 128;
    int lane = tid & 31, warp = tid >> 5;
    int wm = (warp >> 2) * 64, wn = (warp & 3) * 32;
    int g = lane >> 2, tc = lane & 3;

    #pragma unroll
    for (int i = 0; i < 40; i++) {
        int idx = i * 256 + tid;
        int r = idx / 80, c = idx - r * 80;
        int grow = row0 + r;
        float v = (grow < N_NODES && c < FI) ? hval(l, grow, c) : 0.f;
        As[r * AS + c] = tf32r(v);
    }
    #pragma unroll
    for (int i = 0; i < 40; i++) {
        int idx = i * 256 + tid;
        int kr = idx >> 7, c = idx & 127;
        int j = col0 + c;
        float v = 0.f;
        if (kr < FI && j < 750)
            v = (j < MSG_DIM) ? Wt[kr * MSG_DIM + j] : Wt[(FI + kr) * MSG_DIM + (j - MSG_DIM)];
        Bs[kr * BS + c] = tf32r(v);
    }
    __syncthreads();

    float acc[4][4][4];
    #pragma unroll
    for (int i = 0; i < 4; i++)
        #pragma unroll
        for (int j = 0; j < 4; j++)
            #pragma unroll
            for (int q = 0; q < 4; q++) acc[i][j][q] = 0.f;

    #pragma unroll
    for (int kk = 0; kk < 80; kk += 8) {
        uint32_t a[4][4], b[4][2];
        #pragma unroll
        for (int i = 0; i < 4; i++) {
            int m = wm + i * 16 + g;
            a[i][0] = __float_as_uint(As[m * AS + kk + tc]);
            a[i][1] = __float_as_uint(As[(m + 8) * AS + kk + tc]);
            a[i][2] = __float_as_uint(As[m * AS + kk + tc + 4]);
            a[i][3] = __float_as_uint(As[(m + 8) * AS + kk + tc + 4]);
        }
        #pragma unroll
        for (int j = 0; j < 4; j++) {
            int n = wn + j * 8 + g;
            b[j][0] = __float_as_uint(Bs[(kk + tc) * BS + n]);
            b[j][1] = __float_as_uint(Bs[(kk + tc + 4) * BS + n]);
        }
        #pragma unroll
        for (int i = 0; i < 4; i++)
            #pragma unroll
            for (int j = 0; j < 4; j++) mma_tf32(acc[i][j], a[i], b[j]);
    }

    #pragma unroll
    for (int i = 0; i < 4; i++) {
        int r = row0 + wm + i * 16 + g;
        #pragma unroll
        for (int j = 0; j < 4; j++) {
            int cb = col0 + wn + j * 8 + 2 * tc;
            if (cb < 750) {
                int o0 = (cb < MSG_DIM) ? cb : cb + 1;
                float b0 = (cb < MSG_DIM) ? bias[cb] : 0.f;
                if (r < N_NODES) d_P[(size_t)r * PSTRIDE + o0] = acc[i][j][0] + b0;
                if (r + 8 < N_NODES) d_P[(size_t)(r + 8) * PSTRIDE + o0] = acc[i][j][2] + b0;
                if (cb + 1 < 750) {
                    int o1 = (cb + 1 < MSG_DIM) ? cb + 1 : cb + 2;
                    float b1 = (cb + 1 < MSG_DIM) ? bias[cb + 1] : 0.f;
                    if (r < N_NODES) d_P[(size_t)r * PSTRIDE + o1] = acc[i][j][1] + b1;
                    if (r + 8 < N_NODES) d_P[(size_t)(r + 8) * PSTRIDE + o1] = acc[i][j][3] + b1;
                }
            }
        }
    }
}

// ---------------- fused message + aggregation (float2, independent warps) -------------
__global__ void k_agg_fused(int l) {
    int n = blockIdx.x;
    int t = threadIdx.x;            // 192 threads, 188 active (2 cols each)
    if (t >= 188) return;
    int j = 2 * t;
    const float2* P3 = (const float2*)(d_P3 + (size_t)l * 16 * P3STRIDE);
    int s0 = d_rowstart[n], s1 = d_rowstart[n + 1];
    float2 p1 = *(const float2*)(d_P + (size_t)n * PSTRIDE + j);
    float sx = 0.f, sy = 0.f, qx = 0.f, qy = 0.f;
    float mnx = 3.4e38f, mny = 3.4e38f, mxx = -3.4e38f, mxy = -3.4e38f;
    for (int i = s0; i < s1; i++) {
        int sc = d_sc_csr[i];
        int src = sc >> 4, combo = sc & 15;
        float2 p2 = *(const float2*)(d_P + (size_t)src * PSTRIDE + 376 + j);
        float2 p3 = P3[combo * 188 + t];
        float vx = p1.x + p2.x + p3.x;
        float vy = p1.y + p2.y + p3.y;
        sx += vx; sy += vy;
        qx += vx * vx; qy += vy * vy;
        mnx = fminf(mnx, vx); mny = fminf(mny, vy);
        mxx = fmaxf(mxx, vx); mxy = fmaxf(mxy, vy);
    }
    float cnt = (float)(s1 - s0);
    float deg = fmaxf(cnt, 1.f);
    bool empty = (s1 == s0);
    float* abase = d_agg + (size_t)n * 1500;
    #pragma unroll
    for (int k = 0; k < 2; k++) {
        int jj = j + k;
        if (jj >= MSG_DIM) break;
        float s = k ? sy : sx;
        float q = k ? qy : qx;
        float mn = k ? mny : mnx;
        float mx = k ? mxy : mxx;
        float mean = s / deg;
        float var = q / deg - mean * mean;
        if (var < 0.f) var = 0.f;
        float stdv = sqrtf(var + 1e-5f);
        if (empty) { mn = 0.f; mx = 0.f; }
        int tw = jj / FI, f = jj % FI;
        float* a = abase + tw * (4 * FI);
        a[f]          = mean;
        a[FI + f]     = mn;
        a[2 * FI + f] = mx;
        a[3 * FI + f] = stdv;
    }
}

// ---------------- hc GEMM (split-K=2, As reused across both col-blocks) ----------------
__global__ void __launch_bounds__(256, 2) k_gemm_hc(int l) {
    const int AS = 84, BS = 136;
    __shared__ float As[64 * AS];
    __shared__ float Bs[80 * BS];
    const float* WB2 = d_WB2 + (size_t)l * HCK * HCN;
    int tid = threadIdx.x;
    int row0 = blockIdx.x * 64;
    int z = blockIdx.y;
    int lane = tid & 31, warp = tid >> 5;
    int wm = (warp >> 2) * 32, wn = (warp & 3) * 32;
    int g = lane >> 2, tc = lane & 3;

    float acc[2][2][4][4];   // [colpass][i][j][q]
    #pragma unroll
    for (int cb = 0; cb < 2; cb++)
        #pragma unroll
        for (int i = 0; i < 2; i++)
            #pragma unroll
            for (int j = 0; j < 4; j++)
                #pragma unroll
                for (int q = 0; q < 4; q++) acc[cb][i][j][q] = 0.f;

    int kbeg = z * HCK2, kend = kbeg + HCK2;
    for (int k0 = kbeg; k0 < kend; k0 += 80) {
        // As fill once per k-chunk (reused by both column passes)
        #pragma unroll
        for (int i = 0; i < 20; i++) {
            int idx = i * 256 + tid;
            int r = idx / 80, c = idx - r * 80;
            int grow = row0 + r;
            int gc = k0 + c;
            float v = 0.f;
            if (grow < N_NODES) {
                if (gc < 1500) v = d_agg[(size_t)grow * 1500 + gc];
                else if (gc < 1575) v = hval(l, grow, gc - 1500);
            }
            As[r * AS + c] = tf32r(v);
        }
        #pragma unroll
        for (int cb = 0; cb < 2; cb++) {
            int col0 = cb * 128;
            #pragma unroll
            for (int i = 0; i < 40; i++) {
                int idx = i * 256 + tid;
                int kr = idx >> 7, c = idx & 127;
                int j = col0 + c;
                float v = (j < HCN) ? WB2[(size_t)(k0 + kr) * HCN + j] : 0.f;
                Bs[kr * BS + c] = tf32r(v);
            }
            __syncthreads();
            #pragma unroll
            for (int kk = 0; kk < 80; kk += 8) {
                uint32_t a[2][4], b[4][2];
                #pragma unroll
                for (int i = 0; i < 2; i++) {
                    int m = wm + i * 16 + g;
                    a[i][0] = __float_as_uint(As[m * AS + kk + tc]);
                    a[i][1] = __float_as_uint(As[(m + 8) * AS + kk + tc]);
                    a[i][2] = __float_as_uint(As[m * AS + kk + tc + 4]);
                    a[i][3] = __float_as_uint(As[(m + 8) * AS + kk + tc + 4]);
                }
                #pragma unroll
                for (int j = 0; j < 4; j++) {
                    int n = wn + j * 8 + g;
                    b[j][0] = __float_as_uint(Bs[(kk + tc) * BS + n]);
                    b[j][1] = __float_as_uint(Bs[(kk + tc + 4) * BS + n]);
                }
                #pragma unroll
                for (int i = 0; i < 2; i++)
                    #pragma unroll
                    for (int j = 0; j < 4; j++) mma_tf32(acc[cb][i][j], a[i], b[j]);
            }
            __syncthreads();
        }
    }

    float* gout = (z == 0) ? d_G0 : d_G1;
    #pragma unroll
    for (int cb = 0; cb < 2; cb++) {
        int col0 = cb * 128;
        #pragma unroll
        for (int i = 0; i < 2; i++) {
            int r = row0 + wm + i * 16 + g;
            #pragma unroll
            for (int j = 0; j < 4; j++) {
                int cbc = col0 + wn + j * 8 + 2 * tc;
                if (cbc < HCN) {
                    if (r < N_NODES) {
                        gout[(size_t)r * HCN + cbc] = acc[cb][i][j][0];
                        if (cbc + 1 < HCN) gout[(size_t)r * HCN + cbc + 1] = acc[cb][i][j][1];
                    }
                    if (r + 8 < N_NODES) {
                        gout[(size_t)(r + 8) * HCN + cbc] = acc[cb][i][j][2];
                        if (cbc + 1 < HCN) gout[(size_t)(r + 8) * HCN + cbc + 1] = acc[cb][i][j][3];
                    }
                }
            }
        }
    }
}

// ---------------- combine G0+G1 -> hc + BN stats + fused bnfin (last block) ------------
__global__ void k_combine(int l, const float* __restrict__ bn_g, const float* __restrict__ bn_b) {
    __shared__ float ssum[FI], ssq[FI];
    __shared__ bool isLast;
    int tid = threadIdx.x;
    if (tid < FI) { ssum[tid] = 0.f; ssq[tid] = 0.f; }
    __syncthreads();
    const float* bias2 = d_bias2 + l * FI;
    int base = blockIdx.x * 50;
    for (int idx = tid; idx < 50 * FI; idx += blockDim.x) {
        int n = base + idx / FI, f = idx % FI;
        float cnt = (float)(d_rowstart[n + 1] - d_rowstart[n]);
        float log_deg = logf(fmaxf(cnt, 1.f) + 1.f);
        float amp = log_deg / AVG_DEG_LOG;
        float att = AVG_DEG_LOG / log_deg;
        const float* g0 = d_G0 + (size_t)n * HCN;
        const float* g1 = d_G1 + (size_t)n * HCN;
        float v = (g0[f] + g1[f])
                + amp * (g0[FI + f] + g1[FI + f])
                + att * (g0[2 * FI + f] + g1[2 * FI + f]) + bias2[f];
        d_hc[n * FI + f] = v;
        atomicAdd(&ssum[f], v);
        atomicAdd(&ssq[f], v * v);
    }
    __syncthreads();
    if (tid < FI) {
        atomicAdd(&d_bnsum[l * FI + tid], ssum[tid]);
        atomicAdd(&d_bnsq[l * FI + tid], ssq[tid]);
    }
    __threadfence();
    __syncthreads();
    if (tid == 0) {
        int old = atomicAdd(&d_combine_cnt, 1);
        isLast = (old == gridDim.x - 1);
    }
    __syncthreads();
    if (isLast) {
        if (tid < FI) {
            float mu = d_bnsum[l * FI + tid] / (float)N_NODES;
            float var = d_bnsq[l * FI + tid] / (float)N_NODES - mu * mu;
            float sc = bn_g[l * FI + tid] * rsqrtf(var + 1e-5f);
            d_bnscale[l * FI + tid] = sc;
            d_bnshift[l * FI + tid] = bn_b[l * FI + tid] - mu * sc;
        }
        if (tid == 0) d_combine_cnt = 0;
    }
}

// ---------------- pool (BN fused) + MLP --------------------------------------------------
__global__ void k_pool(const int* __restrict__ batch) {
    int idx = blockIdx.x * blockDim.x + threadIdx.x;
    if (idx >= N_NODES * FI) return;
    int n = idx / FI, f = idx % FI;
    int o = (N_LAYERS - 1) * FI + f;
    float v = fmaxf(d_hc[idx] * d_bnscale[o] + d_bnshift[o], 0.f);
    atomicAdd(&d_pool[batch[n] * FI + f], v);
}

__global__ void k_mlp(const float* __restrict__ W1, const float* __restrict__ b1,
                      const float* __restrict__ W2, const float* __restrict__ b2,
                      const float* __restrict__ W3, const float* __restrict__ b3,
                      float* __restrict__ out) {
    __shared__ float g[FI], h1[50], h2[25];
    int gi = blockIdx.x;
    int tid = threadIdx.x;
    if (tid < FI) g[tid] = d_pool[gi * FI + tid];
    __syncthreads();
    if (tid < 50) {
        float a = b1[tid];
        for (int c = 0; c < FI; c++) a += g[c] * W1[c * 50 + tid];
        h1[tid] = fmaxf(a, 0.f);
    }
    __syncthreads();
    if (tid < 25) {
        float a = b2[tid];
        for (int c = 0; c < 50; c++) a += h1[c] * W2[c * 25 + tid];
        h2[tid] = fmaxf(a, 0.f);
    }
    __syncthreads();
    if (tid == 0) {
        float a = b3[0];
        for (int c = 0; c < 25; c++) a += h2[c] * W3[c];
        out[gi] = a;
    }
}

// ---------------- launch --------------------------------------------------------------------
extern "C" void kernel_launch(void* const* d_in, const int* in_sizes, int n_in,
                              void* d_out, int out_size) {
    const int*   x          = (const int*)d_in[0];
    const int*   edge_index = (const int*)d_in[1];
    const int*   edge_attr  = (const int*)d_in[2];
    const int*   batch      = (const int*)d_in[3];
    const float* node_emb   = (const float*)d_in[4];
    const float* edge_emb   = (const float*)d_in[5];
    const float* pre_lin_W  = (const float*)d_in[6];
    const float* pre_lin_b  = (const float*)d_in[7];
    const float* edge_enc_W = (const float*)d_in[8];
    const float* edge_enc_b = (const float*)d_in[9];
    const float* pre_W      = (const float*)d_in[10];
    const float* pre_b      = (const float*)d_in[11];
    const float* post_W     = (const float*)d_in[12];
    const float* post_b     = (const float*)d_in[13];
    const float* lin_W      = (const float*)d_in[14];
    const float* lin_b      = (const float*)d_in[15];
    const float* bn_g       = (const float*)d_in[16];
    const float* bn_b       = (const float*)d_in[17];
    const float* mlp_W1     = (const float*)d_in[18];
    const float* mlp_b1     = (const float*)d_in[19];
    const float* mlp_W2     = (const float*)d_in[20];
    const float* mlp_b2     = (const float*)d_in[21];
    const float* mlp_W3     = (const float*)d_in[22];
    const float* mlp_b3     = (const float*)d_in[23];
    float* out = (float*)d_out;

    // prologue: 5 launches
    k_prep1<<<(PREP1_TOTAL + 255) / 256, 256>>>(x, node_emb, pre_lin_W, pre_lin_b,
                                                pre_W, edge_emb, edge_enc_W, edge_enc_b,
                                                post_W, lin_W, post_b, lin_b);
    k_prep2<<<(N_EDGES + N_LAYERS * 16 * P3STRIDE + 255) / 256, 256>>>(edge_index);
    k_scan<<<1, 1024>>>();
    k_fill<<<(N_EDGES + 255) / 256, 256>>>(edge_index, edge_attr);
    k_gemm_p<<<dim3(6, (N_NODES + 127) / 128), 256>>>(0, pre_b);

    for (int l = 0; l < N_LAYERS; l++) {
        if (l > 0) {
            k_gemm_p<<<dim3(6, (N_NODES + 127) / 128), 256>>>(l, pre_b);
        }
        k_agg_fused<<<N_NODES, 192>>>(l);
        k_gemm_hc<<<dim3((N_NODES + 63) / 64, 2), 256>>>(l);
        k_combine<<<N_NODES / 50, 256>>>(l, bn_g, bn_b);
    }

    k_pool<<<(N_NODES * FI + 255) / 256, 256>>>(batch);
    k_mlp<<<N_GRAPHS, 128>>>(mlp_W1, mlp_b1, mlp_W2, mlp_b2, mlp_W3, mlp_b3, out);
}

// round 14
// speedup vs baseline: 1.0313x; 1.0313x over previous
#include <cuda_runtime.h>
#include <math.h>
#include <stdint.h>

#define N_NODES 10000
#define N_EDGES 160000
#define N_GRAPHS 64
#define T_TOW 5
#define FI 75
#define FO 15
#define N_LAYERS 4
#define MSG_DIM 375        // T*FI
#define MIN_DIM 225
#define OUT_DIM 975
#define POST_DIM 75
#define PSTRIDE 752        // padded P row: [P1 0..374 | pad | P2 376..750 | pad]
#define P3STRIDE 376
#define HCK 1600
#define HCK2 800
#define HCN 225
#define AVG_DEG_LOG 2.8332133440562162f

// prep1 region sizes
#define NT   (N_LAYERS * MIN_DIM * MSG_DIM)
#define NE   (N_LAYERS * 16 * FI)
#define NB2  (N_LAYERS * FI)
#define NBZ  (N_LAYERS * FI)
#define NPZ  (N_GRAPHS * FI)
#define NCZ  (N_NODES)
#define NH0  (N_NODES * FI)
#define NWB  (N_LAYERS * HCK * HCN)
#define PREP1_TOTAL (NT + NE + NB2 + NBZ + NPZ + NCZ + NH0 + NWB)

// ---------------- scratch (device-side access only) -----------------------------
__device__ float d_h[N_NODES * FI];
__device__ float d_hc[N_NODES * FI];
__device__ float d_P[N_NODES * PSTRIDE];           // pads stay 0
__device__ float d_agg[N_NODES * 1500];
__device__ float d_G0[N_NODES * HCN];
__device__ float d_G1[N_NODES * HCN];
__device__ float d_Wt[N_LAYERS * MIN_DIM * MSG_DIM];
__device__ float d_WB2[N_LAYERS * HCK * HCN];
__device__ float d_P3[N_LAYERS * 16 * P3STRIDE];
__device__ float d_enctab[N_LAYERS * 16 * FI];
__device__ float d_bias2[N_LAYERS * FI];
__device__ int   d_cnt[N_NODES];
__device__ int   d_rowstart[N_NODES + 1];
__device__ int   d_cursor[N_NODES];
__device__ int   d_sc_csr[N_EDGES];                // src*16 + combo
__device__ float d_bnsum[N_LAYERS * FI];
__device__ float d_bnsq[N_LAYERS * FI];
__device__ float d_bnscale[N_LAYERS * FI];
__device__ float d_bnshift[N_LAYERS * FI];
__device__ float d_pool[N_GRAPHS * FI];
__device__ int   d_combine_cnt;

__device__ __forceinline__ float tf32r(float v) {
    uint32_t o;
    asm("cvt.rna.tf32.f32 %0, %1;" : "=r"(o) : "f"(v));
    return __uint_as_float(o);
}

__device__ __forceinline__ void mma_tf32(float* c, const uint32_t* a, const uint32_t* b) {
    asm volatile(
        "mma.sync.aligned.m16n8k8.row.col.f32.tf32.tf32.f32 "
        "{%0,%1,%2,%3}, {%4,%5,%6,%7}, {%8,%9}, {%0,%1,%2,%3};"
        : "+f"(c[0]), "+f"(c[1]), "+f"(c[2]), "+f"(c[3])
        : "r"(a[0]), "r"(a[1]), "r"(a[2]), "r"(a[3]), "r"(b[0]), "r"(b[1]));
}

__device__ __forceinline__ float hval(int l, int n, int f) {
    if (l == 0) return d_h[n * FI + f];
    int o = (l - 1) * FI + f;
    return fmaxf(d_hc[n * FI + f] * d_bnscale[o] + d_bnshift[o], 0.f);
}

// ---------------- prep1: all independent prologue work in one launch ----------------
__global__ void k_prep1(const int* __restrict__ x, const float* __restrict__ node_emb,
                        const float* __restrict__ pre_lin_W, const float* __restrict__ pre_lin_b,
                        const float* __restrict__ preW,
                        const float* __restrict__ edge_emb,
                        const float* __restrict__ encW, const float* __restrict__ encb,
                        const float* __restrict__ postW, const float* __restrict__ linW,
                        const float* __restrict__ postb, const float* __restrict__ linb) {
    int idx = blockIdx.x * blockDim.x + threadIdx.x;
    if (idx < NT) {
        int l = idx / (MIN_DIM * MSG_DIM);
        int r = idx % (MIN_DIM * MSG_DIM);
        int c = r / MSG_DIM, j = r % MSG_DIM;
        int t = j / FI, f = j % FI;
        d_Wt[idx] = preW[((size_t)l * T_TOW + t) * MIN_DIM * FI + c * FI + f];
        return;
    }
    idx -= NT;
    if (idx < NE) {
        int l = idx / (16 * FI);
        int r = idx % (16 * FI);
        int combo = r / FI, f = r % FI;
        int a0 = combo >> 2, a1 = combo & 3;
        const float* e0 = edge_emb + a0 * 25;
        const float* e1 = edge_emb + a1 * 25;
        const float* W = encW + l * 50 * FI;
        float acc = encb[l * FI + f];
        #pragma unroll 5
        for (int q = 0; q < 25; q++) acc += e0[q] * W[q * FI + f];
        #pragma unroll 5
        for (int q = 0; q < 25; q++) acc += e1[q] * W[(25 + q) * FI + f];
        d_enctab[idx] = acc;
        return;
    }
    idx -= NE;
    if (idx < NB2) {
        int l = idx / FI, j = idx % FI;
        const float* lW = linW + l * POST_DIM * FI;
        float acc = linb[l * FI + j];
        #pragma unroll 5
        for (int q = 0; q < POST_DIM; q++) acc += postb[l * POST_DIM + q] * lW[q * FI + j];
        d_bias2[idx] = acc;
        return;
    }
    idx -= NB2;
    if (idx < NBZ) { d_bnsum[idx] = 0.f; d_bnsq[idx] = 0.f; return; }
    idx -= NBZ;
    if (idx < NPZ) { d_pool[idx] = 0.f; return; }
    idx -= NPZ;
    if (idx < NCZ) {
        d_cnt[idx] = 0;
        if (idx == 0) d_combine_cnt = 0;
        return;
    }
    idx -= NCZ;
    if (idx < NH0) {
        int n = idx / FI, f = idx % FI;
        int i0 = x[n * 2 + 0], i1 = x[n * 2 + 1];
        const float* e0 = node_emb + i0 * FI;
        const float* e1 = node_emb + i1 * FI;
        float acc = pre_lin_b[f];
        #pragma unroll 5
        for (int c = 0; c < FI; c++) acc += e0[c] * pre_lin_W[c * FI + f];
        #pragma unroll 5
        for (int c = 0; c < FI; c++) acc += e1[c] * pre_lin_W[(FI + c) * FI + f];
        d_h[idx] = acc;
        return;
    }
    idx -= NH0;
    if (idx < NWB) {
        int l = idx / (HCK * HCN);
        int r = idx % (HCK * HCN);
        int k = r / HCN, j = r % HCN;
        const float* pW = postW + (size_t)l * T_TOW * OUT_DIM * FO;
        const float* lW = linW + l * POST_DIM * FI;
        float acc = 0.f;
        if (k < 1500) {
            int t = k / 300, k300 = k % 300;
            int sel = j / FI, jj = j % FI;
            int c = FI + sel * 300 + k300;
            const float* pw = pW + ((size_t)t * OUT_DIM + c) * FO;
            const float* lw = lW + (t * FO) * FI + jj;
            #pragma unroll
            for (int f = 0; f < FO; f++) acc += pw[f] * lw[f * FI];
        } else if (k < 1575 && j < FI) {
            int c = k - 1500;
            #pragma unroll
            for (int t = 0; t < T_TOW; t++) {
                const float* pw = pW + ((size_t)t * OUT_DIM + c) * FO;
                const float* lw = lW + (t * FO) * FI + j;
                #pragma unroll
                for (int f = 0; f < FO; f++) acc += pw[f] * lw[f * FI];
            }
        }
        d_WB2[idx] = acc;
    }
}

// ---------------- prep2: count + P3 ---------------------------------------------------
__global__ void k_prep2(const int* __restrict__ edge_index) {
    int idx = blockIdx.x * blockDim.x + threadIdx.x;
    if (idx < N_EDGES) {
        atomicAdd(&d_cnt[edge_index[N_EDGES + idx]], 1);
        return;
    }
    idx -= N_EDGES;
    if (idx < N_LAYERS * 16 * P3STRIDE) {
        int l = idx / (16 * P3STRIDE);
        int r = idx % (16 * P3STRIDE);
        int combo = r / P3STRIDE, j = r % P3STRIDE;
        float acc = 0.f;
        if (j < MSG_DIM) {
            const float* e = d_enctab + (l * 16 + combo) * FI;
            const float* W = d_Wt + (size_t)l * MIN_DIM * MSG_DIM;
            #pragma unroll 5
            for (int k = 0; k < FI; k++) acc += e[k] * W[(2 * FI + k) * MSG_DIM + j];
        }
        d_P3[idx] = acc;
    }
}

// ---------------- scan + fill ---------------------------------------------------------
__global__ void k_scan() {
    __shared__ int ssum[1024];
    int tid = threadIdx.x;
    const int ITEMS = 10;
    int base = tid * ITEMS;
    int local[ITEMS];
    int s = 0;
    #pragma unroll
    for (int i = 0; i < ITEMS; i++) {
        int g = base + i;
        int v = (g < N_NODES) ? d_cnt[g] : 0;
        local[i] = s;
        s += v;
    }
    ssum[tid] = s;
    __syncthreads();
    for (int off = 1; off < 1024; off <<= 1) {
        int v = (tid >= off) ? ssum[tid - off] : 0;
        __syncthreads();
        ssum[tid] += v;
        __syncthreads();
    }
    int excl = (tid == 0) ? 0 : ssum[tid - 1];
    #pragma unroll
    for (int i = 0; i < ITEMS; i++) {
        int g = base + i;
        if (g < N_NODES) {
            int rs = excl + local[i];
            d_rowstart[g] = rs;
            d_cursor[g]   = rs;
        }
    }
    if (tid == 0) d_rowstart[N_NODES] = ssum[1023];
}

__global__ void k_fill(const int* __restrict__ edge_index, const int* __restrict__ edge_attr) {
    int e = blockIdx.x * blockDim.x + threadIdx.x;
    if (e >= N_EDGES) return;
    int dst = edge_index[N_EDGES + e];
    int pos = atomicAdd(&d_cursor[dst], 1);
    d_sc_csr[pos] = edge_index[e] * 16 + edge_attr[e * 2] * 4 + edge_attr[e * 2 + 1];
}

// ---------------- P GEMM (BM=128): P[n] = [h|h] @ [W1|W2] + [bias|0] ------------------
__global__ void __launch_bounds__(256, 2) k_gemm_p(int l, const float* __restrict__ bias_all) {
    const int AS = 84, BS = 136;
    __shared__ float As[128 * AS];
    __shared__ float Bs[80 * BS];
    const float* Wt = d_Wt + (size_t)l * MIN_DIM * MSG_DIM;
    const float* bias = bias_all + l * MSG_DIM;
    int tid = threadIdx.x;
    int row0 = blockIdx.y * 128;
    int col0 = blockIdx.x * 128;
    int lane = tid & 31, warp = tid >> 5;
    int wm = (warp >> 2) * 64, wn = (warp & 3) * 32;
    int g = lane >> 2, tc = lane & 3;

    #pragma unroll
    for (int i = 0; i < 40; i++) {
        int idx = i * 256 + tid;
        int r = idx / 80, c = idx - r * 80;
        int grow = row0 + r;
        float v = (grow < N_NODES && c < FI) ? hval(l, grow, c) : 0.f;
        As[r * AS + c] = tf32r(v);
    }
    #pragma unroll
    for (int i = 0; i < 40; i++) {
        int idx = i * 256 + tid;
        int kr = idx >> 7, c = idx & 127;
        int j = col0 + c;
        float v = 0.f;
        if (kr < FI && j < 750)
            v = (j < MSG_DIM) ? Wt[kr * MSG_DIM + j] : Wt[(FI + kr) * MSG_DIM + (j - MSG_DIM)];
        Bs[kr * BS + c] = tf32r(v);
    }
    __syncthreads();

    float acc[4][4][4];
    #pragma unroll
    for (int i = 0; i < 4; i++)
        #pragma unroll
        for (int j = 0; j < 4; j++)
            #pragma unroll
            for (int q = 0; q < 4; q++) acc[i][j][q] = 0.f;

    #pragma unroll
    for (int kk = 0; kk < 80; kk += 8) {
        uint32_t a[4][4], b[4][2];
        #pragma unroll
        for (int i = 0; i < 4; i++) {
            int m = wm + i * 16 + g;
            a[i][0] = __float_as_uint(As[m * AS + kk + tc]);
            a[i][1] = __float_as_uint(As[(m + 8) * AS + kk + tc]);
            a[i][2] = __float_as_uint(As[m * AS + kk + tc + 4]);
            a[i][3] = __float_as_uint(As[(m + 8) * AS + kk + tc + 4]);
        }
        #pragma unroll
        for (int j = 0; j < 4; j++) {
            int n = wn + j * 8 + g;
            b[j][0] = __float_as_uint(Bs[(kk + tc) * BS + n]);
            b[j][1] = __float_as_uint(Bs[(kk + tc + 4) * BS + n]);
        }
        #pragma unroll
        for (int i = 0; i < 4; i++)
            #pragma unroll
            for (int j = 0; j < 4; j++) mma_tf32(acc[i][j], a[i], b[j]);
    }

    #pragma unroll
    for (int i = 0; i < 4; i++) {
        int r = row0 + wm + i * 16 + g;
        #pragma unroll
        for (int j = 0; j < 4; j++) {
            int cb = col0 + wn + j * 8 + 2 * tc;
            if (cb < 750) {
                int o0 = (cb < MSG_DIM) ? cb : cb + 1;
                float b0 = (cb < MSG_DIM) ? bias[cb] : 0.f;
                if (r < N_NODES) d_P[(size_t)r * PSTRIDE + o0] = acc[i][j][0] + b0;
                if (r + 8 < N_NODES) d_P[(size_t)(r + 8) * PSTRIDE + o0] = acc[i][j][2] + b0;
                if (cb + 1 < 750) {
                    int o1 = (cb + 1 < MSG_DIM) ? cb + 1 : cb + 2;
                    float b1 = (cb + 1 < MSG_DIM) ? bias[cb + 1] : 0.f;
                    if (r < N_NODES) d_P[(size_t)r * PSTRIDE + o1] = acc[i][j][1] + b1;
                    if (r + 8 < N_NODES) d_P[(size_t)(r + 8) * PSTRIDE + o1] = acc[i][j][3] + b1;
                }
            }
        }
    }
}

// ---------------- fused message + aggregation (float2, independent warps) -------------
__global__ void k_agg_fused(int l) {
    int n = blockIdx.x;
    int t = threadIdx.x;            // 192 threads, 188 active (2 cols each)
    if (t >= 188) return;
    int j = 2 * t;
    const float2* P3 = (const float2*)(d_P3 + (size_t)l * 16 * P3STRIDE);
    int s0 = d_rowstart[n], s1 = d_rowstart[n + 1];
    float2 p1 = *(const float2*)(d_P + (size_t)n * PSTRIDE + j);
    float sx = 0.f, sy = 0.f, qx = 0.f, qy = 0.f;
    float mnx = 3.4e38f, mny = 3.4e38f, mxx = -3.4e38f, mxy = -3.4e38f;
    for (int i = s0; i < s1; i++) {
        int sc = d_sc_csr[i];
        int src = sc >> 4, combo = sc & 15;
        float2 p2 = *(const float2*)(d_P + (size_t)src * PSTRIDE + 376 + j);
        float2 p3 = P3[combo * 188 + t];
        float vx = p1.x + p2.x + p3.x;
        float vy = p1.y + p2.y + p3.y;
        sx += vx; sy += vy;
        qx += vx * vx; qy += vy * vy;
        mnx = fminf(mnx, vx); mny = fminf(mny, vy);
        mxx = fmaxf(mxx, vx); mxy = fmaxf(mxy, vy);
    }
    float cnt = (float)(s1 - s0);
    float deg = fmaxf(cnt, 1.f);
    bool empty = (s1 == s0);
    float* abase = d_agg + (size_t)n * 1500;
    #pragma unroll
    for (int k = 0; k < 2; k++) {
        int jj = j + k;
        if (jj >= MSG_DIM) break;
        float s = k ? sy : sx;
        float q = k ? qy : qx;
        float mn = k ? mny : mnx;
        float mx = k ? mxy : mxx;
        float mean = s / deg;
        float var = q / deg - mean * mean;
        if (var < 0.f) var = 0.f;
        float stdv = sqrtf(var + 1e-5f);
        if (empty) { mn = 0.f; mx = 0.f; }
        int tw = jj / FI, f = jj % FI;
        float* a = abase + tw * (4 * FI);
        a[f]          = mean;
        a[FI + f]     = mn;
        a[2 * FI + f] = mx;
        a[3 * FI + f] = stdv;
    }
}

// ---------------- hc GEMM (split-K=2), BN fused on K-tail -----------------------------
__global__ void __launch_bounds__(256, 2) k_gemm_hc(int l) {
    const int AS = 84, BS = 136;
    __shared__ float As[64 * AS];
    __shared__ float Bs[80 * BS];
    const float* WB2 = d_WB2 + (size_t)l * HCK * HCN;
    int tid = threadIdx.x;
    int row0 = blockIdx.y * 64;
    int col0 = blockIdx.x * 128;
    int z = blockIdx.z;
    int lane = tid & 31, warp = tid >> 5;
    int wm = (warp >> 2) * 32, wn = (warp & 3) * 32;
    int g = lane >> 2, tc = lane & 3;

    float acc[2][4][4];
    #pragma unroll
    for (int i = 0; i < 2; i++)
        #pragma unroll
        for (int j = 0; j < 4; j++)
            #pragma unroll
            for (int q = 0; q < 4; q++) acc[i][j][q] = 0.f;

    int kbeg = z * HCK2, kend = kbeg + HCK2;
    for (int k0 = kbeg; k0 < kend; k0 += 80) {
        #pragma unroll
        for (int i = 0; i < 20; i++) {
            int idx = i * 256 + tid;
            int r = idx / 80, c = idx - r * 80;
            int grow = row0 + r;
            int gc = k0 + c;
            float v = 0.f;
            if (grow < N_NODES) {
                if (gc < 1500) v = d_agg[(size_t)grow * 1500 + gc];
                else if (gc < 1575) v = hval(l, grow, gc - 1500);
            }
            As[r * AS + c] = tf32r(v);
        }
        #pragma unroll
        for (int i = 0; i < 40; i++) {
            int idx = i * 256 + tid;
            int kr = idx >> 7, c = idx & 127;
            int j = col0 + c;
            float v = (j < HCN) ? WB2[(size_t)(k0 + kr) * HCN + j] : 0.f;
            Bs[kr * BS + c] = tf32r(v);
        }
        __syncthreads();
        #pragma unroll
        for (int kk = 0; kk < 80; kk += 8) {
            uint32_t a[2][4], b[4][2];
            #pragma unroll
            for (int i = 0; i < 2; i++) {
                int m = wm + i * 16 + g;
                a[i][0] = __float_as_uint(As[m * AS + kk + tc]);
                a[i][1] = __float_as_uint(As[(m + 8) * AS + kk + tc]);
                a[i][2] = __float_as_uint(As[m * AS + kk + tc + 4]);
                a[i][3] = __float_as_uint(As[(m + 8) * AS + kk + tc + 4]);
            }
            #pragma unroll
            for (int j = 0; j < 4; j++) {
                int n = wn + j * 8 + g;
                b[j][0] = __float_as_uint(Bs[(kk + tc) * BS + n]);
                b[j][1] = __float_as_uint(Bs[(kk + tc + 4) * BS + n]);
            }
            #pragma unroll
            for (int i = 0; i < 2; i++)
                #pragma unroll
                for (int j = 0; j < 4; j++) mma_tf32(acc[i][j], a[i], b[j]);
        }
        __syncthreads();
    }

    float* gout = (z == 0) ? d_G0 : d_G1;
    #pragma unroll
    for (int i = 0; i < 2; i++) {
        int r = row0 + wm + i * 16 + g;
        #pragma unroll
        for (int j = 0; j < 4; j++) {
            int cb = col0 + wn + j * 8 + 2 * tc;
            if (cb < HCN) {
                if (r < N_NODES) {
                    gout[(size_t)r * HCN + cb] = acc[i][j][0];
                    if (cb + 1 < HCN) gout[(size_t)r * HCN + cb + 1] = acc[i][j][1];
                }
                if (r + 8 < N_NODES) {
                    gout[(size_t)(r + 8) * HCN + cb] = acc[i][j][2];
                    if (cb + 1 < HCN) gout[(size_t)(r + 8) * HCN + cb + 1] = acc[i][j][3];
                }
            }
        }
    }
}

// ---------------- combine G0+G1 -> hc + BN stats + fused bnfin (last block) ------------
__global__ void k_combine(int l, const float* __restrict__ bn_g, const float* __restrict__ bn_b) {
    __shared__ float ssum[FI], ssq[FI];
    __shared__ bool isLast;
    int tid = threadIdx.x;
    if (tid < FI) { ssum[tid] = 0.f; ssq[tid] = 0.f; }
    __syncthreads();
    const float* bias2 = d_bias2 + l * FI;
    int base = blockIdx.x * 50;
    for (int idx = tid; idx < 50 * FI; idx += blockDim.x) {
        int n = base + idx / FI, f = idx % FI;
        float cnt = (float)(d_rowstart[n + 1] - d_rowstart[n]);
        float log_deg = logf(fmaxf(cnt, 1.f) + 1.f);
        float amp = log_deg / AVG_DEG_LOG;
        float att = AVG_DEG_LOG / log_deg;
        const float* g0 = d_G0 + (size_t)n * HCN;
        const float* g1 = d_G1 + (size_t)n * HCN;
        float v = (g0[f] + g1[f])
                + amp * (g0[FI + f] + g1[FI + f])
                + att * (g0[2 * FI + f] + g1[2 * FI + f]) + bias2[f];
        d_hc[n * FI + f] = v;
        atomicAdd(&ssum[f], v);
        atomicAdd(&ssq[f], v * v);
    }
    __syncthreads();
    if (tid < FI) {
        atomicAdd(&d_bnsum[l * FI + tid], ssum[tid]);
        atomicAdd(&d_bnsq[l * FI + tid], ssq[tid]);
    }
    __threadfence();
    __syncthreads();
    if (tid == 0) {
        int old = atomicAdd(&d_combine_cnt, 1);
        isLast = (old == gridDim.x - 1);
    }
    __syncthreads();
    if (isLast) {
        if (tid < FI) {
            float mu = d_bnsum[l * FI + tid] / (float)N_NODES;
            float var = d_bnsq[l * FI + tid] / (float)N_NODES - mu * mu;
            float sc = bn_g[l * FI + tid] * rsqrtf(var + 1e-5f);
            d_bnscale[l * FI + tid] = sc;
            d_bnshift[l * FI + tid] = bn_b[l * FI + tid] - mu * sc;
        }
        if (tid == 0) d_combine_cnt = 0;
    }
}

// ---------------- pool (BN fused) + MLP --------------------------------------------------
__global__ void k_pool(const int* __restrict__ batch) {
    int idx = blockIdx.x * blockDim.x + threadIdx.x;
    if (idx >= N_NODES * FI) return;
    int n = idx / FI, f = idx % FI;
    int o = (N_LAYERS - 1) * FI + f;
    float v = fmaxf(d_hc[idx] * d_bnscale[o] + d_bnshift[o], 0.f);
    atomicAdd(&d_pool[batch[n] * FI + f], v);
}

__global__ void k_mlp(const float* __restrict__ W1, const float* __restrict__ b1,
                      const float* __restrict__ W2, const float* __restrict__ b2,
                      const float* __restrict__ W3, const float* __restrict__ b3,
                      float* __restrict__ out) {
    __shared__ float g[FI], h1[50], h2[25];
    int gi = blockIdx.x;
    int tid = threadIdx.x;
    if (tid < FI) g[tid] = d_pool[gi * FI + tid];
    __syncthreads();
    if (tid < 50) {
        float a = b1[tid];
        for (int c = 0; c < FI; c++) a += g[c] * W1[c * 50 + tid];
        h1[tid] = fmaxf(a, 0.f);
    }
    __syncthreads();
    if (tid < 25) {
        float a = b2[tid];
        for (int c = 0; c < 50; c++) a += h1[c] * W2[c * 25 + tid];
        h2[tid] = fmaxf(a, 0.f);
    }
    __syncthreads();
    if (tid == 0) {
        float a = b3[0];
        for (int c = 0; c < 25; c++) a += h2[c] * W3[c];
        out[gi] = a;
    }
}

// ---------------- launch --------------------------------------------------------------------
extern "C" void kernel_launch(void* const* d_in, const int* in_sizes, int n_in,
                              void* d_out, int out_size) {
    const int*   x          = (const int*)d_in[0];
    const int*   edge_index = (const int*)d_in[1];
    const int*   edge_attr  = (const int*)d_in[2];
    const int*   batch      = (const int*)d_in[3];
    const float* node_emb   = (const float*)d_in[4];
    const float* edge_emb   = (const float*)d_in[5];
    const float* pre_lin_W  = (const float*)d_in[6];
    const float* pre_lin_b  = (const float*)d_in[7];
    const float* edge_enc_W = (const float*)d_in[8];
    const float* edge_enc_b = (const float*)d_in[9];
    const float* pre_W      = (const float*)d_in[10];
    const float* pre_b      = (const float*)d_in[11];
    const float* post_W     = (const float*)d_in[12];
    const float* post_b     = (const float*)d_in[13];
    const float* lin_W      = (const float*)d_in[14];
    const float* lin_b      = (const float*)d_in[15];
    const float* bn_g       = (const float*)d_in[16];
    const float* bn_b       = (const float*)d_in[17];
    const float* mlp_W1     = (const float*)d_in[18];
    const float* mlp_b1     = (const float*)d_in[19];
    const float* mlp_W2     = (const float*)d_in[20];
    const float* mlp_b2     = (const float*)d_in[21];
    const float* mlp_W3     = (const float*)d_in[22];
    const float* mlp_b3     = (const float*)d_in[23];
    float* out = (float*)d_out;

    // prologue: 5 launches
    k_prep1<<<(PREP1_TOTAL + 255) / 256, 256>>>(x, node_emb, pre_lin_W, pre_lin_b,
                                                pre_W, edge_emb, edge_enc_W, edge_enc_b,
                                                post_W, lin_W, post_b, lin_b);
    k_prep2<<<(N_EDGES + N_LAYERS * 16 * P3STRIDE + 255) / 256, 256>>>(edge_index);
    k_scan<<<1, 1024>>>();
    k_fill<<<(N_EDGES + 255) / 256, 256>>>(edge_index, edge_attr);
    k_gemm_p<<<dim3(6, (N_NODES + 127) / 128), 256>>>(0, pre_b);

    for (int l = 0; l < N_LAYERS; l++) {
        if (l > 0) {
            k_gemm_p<<<dim3(6, (N_NODES + 127) / 128), 256>>>(l, pre_b);
        }
        k_agg_fused<<<N_NODES, 192>>>(l);
        k_gemm_hc<<<dim3(2, (N_NODES + 63) / 64, 2), 256>>>(l);
        k_combine<<<N_NODES / 50, 256>>>(l, bn_g, bn_b);
    }

    k_pool<<<(N_NODES * FI + 255) / 256, 256>>>(batch);
    k_mlp<<<N_GRAPHS, 128>>>(mlp_W1, mlp_b1, mlp_W2, mlp_b2, mlp_W3, mlp_b3, out);
}

// round 15
// speedup vs baseline: 1.0378x; 1.0064x over previous
#include <cuda_runtime.h>
#include <math.h>
#include <stdint.h>

#define N_NODES 10000
#define N_EDGES 160000
#define N_GRAPHS 64
#define T_TOW 5
#define FI 75
#define FO 15
#define N_LAYERS 4
#define MSG_DIM 375        // T*FI
#define MIN_DIM 225
#define OUT_DIM 975
#define POST_DIM 75
#define PSTRIDE 752        // padded P row: [P1 0..374 | pad | P2 376..750 | pad]
#define P3STRIDE 376
#define HCK 1600
#define HCK2 800
#define HCN 225
#define AVG_DEG_LOG 2.8332133440562162f

// prep1 region sizes
#define NT   (N_LAYERS * MIN_DIM * MSG_DIM)
#define NE   (N_LAYERS * 16 * FI)
#define NB2  (N_LAYERS * FI)
#define NBZ  (N_LAYERS * FI)
#define NPZ  (N_GRAPHS * FI)
#define NCZ  (N_NODES)
#define NH0  (N_NODES * FI)
#define NWB  (N_LAYERS * HCK * HCN)
#define PREP1_TOTAL (NT + NE + NB2 + NBZ + NPZ + NCZ + NH0 + NWB)

// ---------------- scratch (device-side access only) -----------------------------
__device__ float d_h[N_NODES * FI];
__device__ float d_hc[N_NODES * FI];
__device__ float d_P[N_NODES * PSTRIDE];           // pads stay 0
__device__ float d_agg[N_NODES * 1500];
__device__ float d_G0[N_NODES * HCN];
__device__ float d_G1[N_NODES * HCN];
__device__ float d_Wt[N_LAYERS * MIN_DIM * MSG_DIM];
__device__ float d_WB2[N_LAYERS * HCK * HCN];
__device__ float d_P3[N_LAYERS * 16 * P3STRIDE];
__device__ float d_enctab[N_LAYERS * 16 * FI];
__device__ float d_bias2[N_LAYERS * FI];
__device__ int   d_cnt[N_NODES];
__device__ int   d_rowstart[N_NODES + 1];
__device__ int   d_cursor[N_NODES];
__device__ int   d_sc_csr[N_EDGES];                // src*16 + combo
__device__ int   d_gstart[N_GRAPHS + 1];
__device__ float d_bnsum[N_LAYERS * FI];
__device__ float d_bnsq[N_LAYERS * FI];
__device__ float d_bnscale[N_LAYERS * FI];
__device__ float d_bnshift[N_LAYERS * FI];
__device__ float d_pool[N_GRAPHS * FI];
__device__ int   d_combine_cnt;

__device__ __forceinline__ float tf32r(float v) {
    uint32_t o;
    asm("cvt.rna.tf32.f32 %0, %1;" : "=r"(o) : "f"(v));
    return __uint_as_float(o);
}

__device__ __forceinline__ void mma_tf32(float* c, const uint32_t* a, const uint32_t* b) {
    asm volatile(
        "mma.sync.aligned.m16n8k8.row.col.f32.tf32.tf32.f32 "
        "{%0,%1,%2,%3}, {%4,%5,%6,%7}, {%8,%9}, {%0,%1,%2,%3};"
        : "+f"(c[0]), "+f"(c[1]), "+f"(c[2]), "+f"(c[3])
        : "r"(a[0]), "r"(a[1]), "r"(a[2]), "r"(a[3]), "r"(b[0]), "r"(b[1]));
}

__device__ __forceinline__ float hval(int l, int n, int f) {
    if (l == 0) return d_h[n * FI + f];
    int o = (l - 1) * FI + f;
    return fmaxf(d_hc[n * FI + f] * d_bnscale[o] + d_bnshift[o], 0.f);
}

// ---------------- prep1: all independent prologue work in one launch ----------------
__global__ void k_prep1(const int* __restrict__ x, const float* __restrict__ node_emb,
                        const float* __restrict__ pre_lin_W, const float* __restrict__ pre_lin_b,
                        const float* __restrict__ preW,
                        const float* __restrict__ edge_emb,
                        const float* __restrict__ encW, const float* __restrict__ encb,
                        const float* __restrict__ postW, const float* __restrict__ linW,
                        const float* __restrict__ postb, const float* __restrict__ linb) {
    int idx = blockIdx.x * blockDim.x + threadIdx.x;
    if (idx < NT) {
        int l = idx / (MIN_DIM * MSG_DIM);
        int r = idx % (MIN_DIM * MSG_DIM);
        int c = r / MSG_DIM, j = r % MSG_DIM;
        int t = j / FI, f = j % FI;
        d_Wt[idx] = preW[((size_t)l * T_TOW + t) * MIN_DIM * FI + c * FI + f];
        return;
    }
    idx -= NT;
    if (idx < NE) {
        int l = idx / (16 * FI);
        int r = idx % (16 * FI);
        int combo = r / FI, f = r % FI;
        int a0 = combo >> 2, a1 = combo & 3;
        const float* e0 = edge_emb + a0 * 25;
        const float* e1 = edge_emb + a1 * 25;
        const float* W = encW + l * 50 * FI;
        float acc = encb[l * FI + f];
        #pragma unroll 5
        for (int q = 0; q < 25; q++) acc += e0[q] * W[q * FI + f];
        #pragma unroll 5
        for (int q = 0; q < 25; q++) acc += e1[q] * W[(25 + q) * FI + f];
        d_enctab[idx] = acc;
        return;
    }
    idx -= NE;
    if (idx < NB2) {
        int l = idx / FI, j = idx % FI;
        const float* lW = linW + l * POST_DIM * FI;
        float acc = linb[l * FI + j];
        #pragma unroll 5
        for (int q = 0; q < POST_DIM; q++) acc += postb[l * POST_DIM + q] * lW[q * FI + j];
        d_bias2[idx] = acc;
        return;
    }
    idx -= NB2;
    if (idx < NBZ) { d_bnsum[idx] = 0.f; d_bnsq[idx] = 0.f; return; }
    idx -= NBZ;
    if (idx < NPZ) { d_pool[idx] = 0.f; return; }
    idx -= NPZ;
    if (idx < NCZ) {
        d_cnt[idx] = 0;
        if (idx == 0) d_combine_cnt = 0;
        return;
    }
    idx -= NCZ;
    if (idx < NH0) {
        int n = idx / FI, f = idx % FI;
        int i0 = x[n * 2 + 0], i1 = x[n * 2 + 1];
        const float* e0 = node_emb + i0 * FI;
        const float* e1 = node_emb + i1 * FI;
        float acc = pre_lin_b[f];
        #pragma unroll 5
        for (int c = 0; c < FI; c++) acc += e0[c] * pre_lin_W[c * FI + f];
        #pragma unroll 5
        for (int c = 0; c < FI; c++) acc += e1[c] * pre_lin_W[(FI + c) * FI + f];
        d_h[idx] = acc;
        return;
    }
    idx -= NH0;
    if (idx < NWB) {
        int l = idx / (HCK * HCN);
        int r = idx % (HCK * HCN);
        int k = r / HCN, j = r % HCN;
        const float* pW = postW + (size_t)l * T_TOW * OUT_DIM * FO;
        const float* lW = linW + l * POST_DIM * FI;
        float acc = 0.f;
        if (k < 1500) {
            int t = k / 300, k300 = k % 300;
            int sel = j / FI, jj = j % FI;
            int c = FI + sel * 300 + k300;
            const float* pw = pW + ((size_t)t * OUT_DIM + c) * FO;
            const float* lw = lW + (t * FO) * FI + jj;
            #pragma unroll
            for (int f = 0; f < FO; f++) acc += pw[f] * lw[f * FI];
        } else if (k < 1575 && j < FI) {
            int c = k - 1500;
            #pragma unroll
            for (int t = 0; t < T_TOW; t++) {
                const float* pw = pW + ((size_t)t * OUT_DIM + c) * FO;
                const float* lw = lW + (t * FO) * FI + j;
                #pragma unroll
                for (int f = 0; f < FO; f++) acc += pw[f] * lw[f * FI];
            }
        }
        d_WB2[idx] = acc;
    }
}

// ---------------- prep2: count + P3 + graph segment starts --------------------------
__global__ void k_prep2(const int* __restrict__ edge_index, const int* __restrict__ batch) {
    int idx = blockIdx.x * blockDim.x + threadIdx.x;
    if (idx < N_EDGES) {
        atomicAdd(&d_cnt[edge_index[N_EDGES + idx]], 1);
        return;
    }
    idx -= N_EDGES;
    if (idx < N_LAYERS * 16 * P3STRIDE) {
        int l = idx / (16 * P3STRIDE);
        int r = idx % (16 * P3STRIDE);
        int combo = r / P3STRIDE, j = r % P3STRIDE;
        float acc = 0.f;
        if (j < MSG_DIM) {
            const float* e = d_enctab + (l * 16 + combo) * FI;
            const float* W = d_Wt + (size_t)l * MIN_DIM * MSG_DIM;
            #pragma unroll 5
            for (int k = 0; k < FI; k++) acc += e[k] * W[(2 * FI + k) * MSG_DIM + j];
        }
        d_P3[idx] = acc;
        return;
    }
    idx -= N_LAYERS * 16 * P3STRIDE;
    if (idx < N_NODES) {
        int n = idx;
        int b = batch[n];
        int pb = (n > 0) ? batch[n - 1] : -1;
        for (int g = pb + 1; g <= b; g++) d_gstart[g] = n;
        if (n == N_NODES - 1) {
            for (int g = b + 1; g <= N_GRAPHS; g++) d_gstart[g] = N_NODES;
        }
    }
}

// ---------------- scan + fill ---------------------------------------------------------
__global__ void k_scan() {
    __shared__ int ssum[1024];
    int tid = threadIdx.x;
    const int ITEMS = 10;
    int base = tid * ITEMS;
    int local[ITEMS];
    int s = 0;
    #pragma unroll
    for (int i = 0; i < ITEMS; i++) {
        int g = base + i;
        int v = (g < N_NODES) ? d_cnt[g] : 0;
        local[i] = s;
        s += v;
    }
    ssum[tid] = s;
    __syncthreads();
    for (int off = 1; off < 1024; off <<= 1) {
        int v = (tid >= off) ? ssum[tid - off] : 0;
        __syncthreads();
        ssum[tid] += v;
        __syncthreads();
    }
    int excl = (tid == 0) ? 0 : ssum[tid - 1];
    #pragma unroll
    for (int i = 0; i < ITEMS; i++) {
        int g = base + i;
        if (g < N_NODES) {
            int rs = excl + local[i];
            d_rowstart[g] = rs;
            d_cursor[g]   = rs;
        }
    }
    if (tid == 0) d_rowstart[N_NODES] = ssum[1023];
}

__global__ void k_fill(const int* __restrict__ edge_index, const int* __restrict__ edge_attr) {
    int e = blockIdx.x * blockDim.x + threadIdx.x;
    if (e >= N_EDGES) return;
    int dst = edge_index[N_EDGES + e];
    int pos = atomicAdd(&d_cursor[dst], 1);
    d_sc_csr[pos] = edge_index[e] * 16 + edge_attr[e * 2] * 4 + edge_attr[e * 2 + 1];
}

// ---------------- P GEMM (BM=128): P[n] = [h|h] @ [W1|W2] + [bias|0] ------------------
__global__ void __launch_bounds__(256, 2) k_gemm_p(int l, const float* __restrict__ bias_all) {
    const int AS = 84, BS = 136;
    __shared__ float As[128 * AS];
    __shared__ float Bs[80 * BS];
    const float* Wt = d_Wt + (size_t)l * MIN_DIM * MSG_DIM;
    const float* bias = bias_all + l * MSG_DIM;
    int tid = threadIdx.x;
    int row0 = blockIdx.y * 128;
    int col0 = blockIdx.x * 128;
    int lane = tid & 31, warp = tid >> 5;
    int wm = (warp >> 2) * 64, wn = (warp & 3) * 32;
    int g = lane >> 2, tc = lane & 3;

    #pragma unroll
    for (int i = 0; i < 40; i++) {
        int idx = i * 256 + tid;
        int r = idx / 80, c = idx - r * 80;
        int grow = row0 + r;
        float v = (grow < N_NODES && c < FI) ? hval(l, grow, c) : 0.f;
        As[r * AS + c] = tf32r(v);
    }
    #pragma unroll
    for (int i = 0; i < 40; i++) {
        int idx = i * 256 + tid;
        int kr = idx >> 7, c = idx & 127;
        int j = col0 + c;
        float v = 0.f;
        if (kr < FI && j < 750)
            v = (j < MSG_DIM) ? Wt[kr * MSG_DIM + j] : Wt[(FI + kr) * MSG_DIM + (j - MSG_DIM)];
        Bs[kr * BS + c] = tf32r(v);
    }
    __syncthreads();

    float acc[4][4][4];
    #pragma unroll
    for (int i = 0; i < 4; i++)
        #pragma unroll
        for (int j = 0; j < 4; j++)
            #pragma unroll
            for (int q = 0; q < 4; q++) acc[i][j][q] = 0.f;

    #pragma unroll
    for (int kk = 0; kk < 80; kk += 8) {
        uint32_t a[4][4], b[4][2];
        #pragma unroll
        for (int i = 0; i < 4; i++) {
            int m = wm + i * 16 + g;
            a[i][0] = __float_as_uint(As[m * AS + kk + tc]);
            a[i][1] = __float_as_uint(As[(m + 8) * AS + kk + tc]);
            a[i][2] = __float_as_uint(As[m * AS + kk + tc + 4]);
            a[i][3] = __float_as_uint(As[(m + 8) * AS + kk + tc + 4]);
        }
        #pragma unroll
        for (int j = 0; j < 4; j++) {
            int n = wn + j * 8 + g;
            b[j][0] = __float_as_uint(Bs[(kk + tc) * BS + n]);
            b[j][1] = __float_as_uint(Bs[(kk + tc + 4) * BS + n]);
        }
        #pragma unroll
        for (int i = 0; i < 4; i++)
            #pragma unroll
            for (int j = 0; j < 4; j++) mma_tf32(acc[i][j], a[i], b[j]);
    }

    #pragma unroll
    for (int i = 0; i < 4; i++) {
        int r = row0 + wm + i * 16 + g;
        #pragma unroll
        for (int j = 0; j < 4; j++) {
            int cb = col0 + wn + j * 8 + 2 * tc;
            if (cb < 750) {
                int o0 = (cb < MSG_DIM) ? cb : cb + 1;
                float b0 = (cb < MSG_DIM) ? bias[cb] : 0.f;
                if (r < N_NODES) d_P[(size_t)r * PSTRIDE + o0] = acc[i][j][0] + b0;
                if (r + 8 < N_NODES) d_P[(size_t)(r + 8) * PSTRIDE + o0] = acc[i][j][2] + b0;
                if (cb + 1 < 750) {
                    int o1 = (cb + 1 < MSG_DIM) ? cb + 1 : cb + 2;
                    float b1 = (cb + 1 < MSG_DIM) ? bias[cb + 1] : 0.f;
                    if (r < N_NODES) d_P[(size_t)r * PSTRIDE + o1] = acc[i][j][1] + b1;
                    if (r + 8 < N_NODES) d_P[(size_t)(r + 8) * PSTRIDE + o1] = acc[i][j][3] + b1;
                }
            }
        }
    }
}

// ---------------- fused message + aggregation (float2, independent warps) -------------
__global__ void k_agg_fused(int l) {
    int n = blockIdx.x;
    int t = threadIdx.x;            // 192 threads, 188 active (2 cols each)
    if (t >= 188) return;
    int j = 2 * t;
    const float2* P3 = (const float2*)(d_P3 + (size_t)l * 16 * P3STRIDE);
    int s0 = d_rowstart[n], s1 = d_rowstart[n + 1];
    float2 p1 = *(const float2*)(d_P + (size_t)n * PSTRIDE + j);
    float sx = 0.f, sy = 0.f, qx = 0.f, qy = 0.f;
    float mnx = 3.4e38f, mny = 3.4e38f, mxx = -3.4e38f, mxy = -3.4e38f;
    for (int i = s0; i < s1; i++) {
        int sc = d_sc_csr[i];
        int src = sc >> 4, combo = sc & 15;
        float2 p2 = *(const float2*)(d_P + (size_t)src * PSTRIDE + 376 + j);
        float2 p3 = P3[combo * 188 + t];
        float vx = p1.x + p2.x + p3.x;
        float vy = p1.y + p2.y + p3.y;
        sx += vx; sy += vy;
        qx += vx * vx; qy += vy * vy;
        mnx = fminf(mnx, vx); mny = fminf(mny, vy);
        mxx = fmaxf(mxx, vx); mxy = fmaxf(mxy, vy);
    }
    float cnt = (float)(s1 - s0);
    float deg = fmaxf(cnt, 1.f);
    bool empty = (s1 == s0);
    float* abase = d_agg + (size_t)n * 1500;
    #pragma unroll
    for (int k = 0; k < 2; k++) {
        int jj = j + k;
        if (jj >= MSG_DIM) break;
        float s = k ? sy : sx;
        float q = k ? qy : qx;
        float mn = k ? mny : mnx;
        float mx = k ? mxy : mxx;
        float mean = s / deg;
        float var = q / deg - mean * mean;
        if (var < 0.f) var = 0.f;
        float stdv = sqrtf(var + 1e-5f);
        if (empty) { mn = 0.f; mx = 0.f; }
        int tw = jj / FI, f = jj % FI;
        float* a = abase + tw * (4 * FI);
        a[f]          = mean;
        a[FI + f]     = mn;
        a[2 * FI + f] = mx;
        a[3 * FI + f] = stdv;
    }
}

// ---------------- hc GEMM (split-K=2), BN fused on K-tail -----------------------------
__global__ void __launch_bounds__(256, 2) k_gemm_hc(int l) {
    const int AS = 84, BS = 136;
    __shared__ float As[64 * AS];
    __shared__ float Bs[80 * BS];
    const float* WB2 = d_WB2 + (size_t)l * HCK * HCN;
    int tid = threadIdx.x;
    int row0 = blockIdx.y * 64;
    int col0 = blockIdx.x * 128;
    int z = blockIdx.z;
    int lane = tid & 31, warp = tid >> 5;
    int wm = (warp >> 2) * 32, wn = (warp & 3) * 32;
    int g = lane >> 2, tc = lane & 3;

    float acc[2][4][4];
    #pragma unroll
    for (int i = 0; i < 2; i++)
        #pragma unroll
        for (int j = 0; j < 4; j++)
            #pragma unroll
            for (int q = 0; q < 4; q++) acc[i][j][q] = 0.f;

    int kbeg = z * HCK2, kend = kbeg + HCK2;
    for (int k0 = kbeg; k0 < kend; k0 += 80) {
        #pragma unroll
        for (int i = 0; i < 20; i++) {
            int idx = i * 256 + tid;
            int r = idx / 80, c = idx - r * 80;
            int grow = row0 + r;
            int gc = k0 + c;
            float v = 0.f;
            if (grow < N_NODES) {
                if (gc < 1500) v = d_agg[(size_t)grow * 1500 + gc];
                else if (gc < 1575) v = hval(l, grow, gc - 1500);
            }
            As[r * AS + c] = tf32r(v);
        }
        #pragma unroll
        for (int i = 0; i < 40; i++) {
            int idx = i * 256 + tid;
            int kr = idx >> 7, c = idx & 127;
            int j = col0 + c;
            float v = (j < HCN) ? WB2[(size_t)(k0 + kr) * HCN + j] : 0.f;
            Bs[kr * BS + c] = tf32r(v);
        }
        __syncthreads();
        #pragma unroll
        for (int kk = 0; kk < 80; kk += 8) {
            uint32_t a[2][4], b[4][2];
            #pragma unroll
            for (int i = 0; i < 2; i++) {
                int m = wm + i * 16 + g;
                a[i][0] = __float_as_uint(As[m * AS + kk + tc]);
                a[i][1] = __float_as_uint(As[(m + 8) * AS + kk + tc]);
                a[i][2] = __float_as_uint(As[m * AS + kk + tc + 4]);
                a[i][3] = __float_as_uint(As[(m + 8) * AS + kk + tc + 4]);
            }
            #pragma unroll
            for (int j = 0; j < 4; j++) {
                int n = wn + j * 8 + g;
                b[j][0] = __float_as_uint(Bs[(kk + tc) * BS + n]);
                b[j][1] = __float_as_uint(Bs[(kk + tc + 4) * BS + n]);
            }
            #pragma unroll
            for (int i = 0; i < 2; i++)
                #pragma unroll
                for (int j = 0; j < 4; j++) mma_tf32(acc[i][j], a[i], b[j]);
        }
        __syncthreads();
    }

    float* gout = (z == 0) ? d_G0 : d_G1;
    #pragma unroll
    for (int i = 0; i < 2; i++) {
        int r = row0 + wm + i * 16 + g;
        #pragma unroll
        for (int j = 0; j < 4; j++) {
            int cb = col0 + wn + j * 8 + 2 * tc;
            if (cb < HCN) {
                if (r < N_NODES) {
                    gout[(size_t)r * HCN + cb] = acc[i][j][0];
                    if (cb + 1 < HCN) gout[(size_t)r * HCN + cb + 1] = acc[i][j][1];
                }
                if (r + 8 < N_NODES) {
                    gout[(size_t)(r + 8) * HCN + cb] = acc[i][j][2];
                    if (cb + 1 < HCN) gout[(size_t)(r + 8) * HCN + cb + 1] = acc[i][j][3];
                }
            }
        }
    }
}

// ---------------- combine G0+G1 -> hc + BN stats + fused bnfin (last block) ------------
__global__ void k_combine(int l, const float* __restrict__ bn_g, const float* __restrict__ bn_b) {
    __shared__ float ssum[FI], ssq[FI];
    __shared__ bool isLast;
    int tid = threadIdx.x;
    if (tid < FI) { ssum[tid] = 0.f; ssq[tid] = 0.f; }
    __syncthreads();
    const float* bias2 = d_bias2 + l * FI;
    int base = blockIdx.x * 25;
    for (int idx = tid; idx < 25 * FI; idx += blockDim.x) {
        int n = base + idx / FI, f = idx % FI;
        float cnt = (float)(d_rowstart[n + 1] - d_rowstart[n]);
        float log_deg = logf(fmaxf(cnt, 1.f) + 1.f);
        float amp = log_deg / AVG_DEG_LOG;
        float att = AVG_DEG_LOG / log_deg;
        const float* g0 = d_G0 + (size_t)n * HCN;
        const float* g1 = d_G1 + (size_t)n * HCN;
        float v = (g0[f] + g1[f])
                + amp * (g0[FI + f] + g1[FI + f])
                + att * (g0[2 * FI + f] + g1[2 * FI + f]) + bias2[f];
        d_hc[n * FI + f] = v;
        atomicAdd(&ssum[f], v);
        atomicAdd(&ssq[f], v * v);
    }
    __syncthreads();
    if (tid < FI) {
        atomicAdd(&d_bnsum[l * FI + tid], ssum[tid]);
        atomicAdd(&d_bnsq[l * FI + tid], ssq[tid]);
    }
    __threadfence();
    __syncthreads();
    if (tid == 0) {
        int old = atomicAdd(&d_combine_cnt, 1);
        isLast = (old == gridDim.x - 1);
    }
    __syncthreads();
    if (isLast) {
        if (tid < FI) {
            float mu = d_bnsum[l * FI + tid] / (float)N_NODES;
            float var = d_bnsq[l * FI + tid] / (float)N_NODES - mu * mu;
            float sc = bn_g[l * FI + tid] * rsqrtf(var + 1e-5f);
            d_bnscale[l * FI + tid] = sc;
            d_bnshift[l * FI + tid] = bn_b[l * FI + tid] - mu * sc;
        }
        if (tid == 0) d_combine_cnt = 0;
    }
}

// ---------------- pool: per-graph segment reduce (BN fused, no atomics) ------------------
__global__ void k_pool() {
    int gi = blockIdx.x;
    int f = threadIdx.x;
    if (f >= FI) return;
    int n0 = d_gstart[gi], n1 = d_gstart[gi + 1];
    int o = (N_LAYERS - 1) * FI + f;
    float sc = d_bnscale[o], sh = d_bnshift[o];
    float acc = 0.f;
    for (int n = n0; n < n1; n++) {
        float v = d_hc[n * FI + f] * sc + sh;
        acc += fmaxf(v, 0.f);
    }
    d_pool[gi * FI + f] = acc;
}

__global__ void k_mlp(const float* __restrict__ W1, const float* __restrict__ b1,
                      const float* __restrict__ W2, const float* __restrict__ b2,
                      const float* __restrict__ W3, const float* __restrict__ b3,
                      float* __restrict__ out) {
    __shared__ float g[FI], h1[50], h2[25];
    int gi = blockIdx.x;
    int tid = threadIdx.x;
    if (tid < FI) g[tid] = d_pool[gi * FI + tid];
    __syncthreads();
    if (tid < 50) {
        float a = b1[tid];
        for (int c = 0; c < FI; c++) a += g[c] * W1[c * 50 + tid];
        h1[tid] = fmaxf(a, 0.f);
    }
    __syncthreads();
    if (tid < 25) {
        float a = b2[tid];
        for (int c = 0; c < 50; c++) a += h1[c] * W2[c * 25 + tid];
        h2[tid] = fmaxf(a, 0.f);
    }
    __syncthreads();
    if (tid == 0) {
        float a = b3[0];
        for (int c = 0; c < 25; c++) a += h2[c] * W3[c];
        out[gi] = a;
    }
}

// ---------------- launch --------------------------------------------------------------------
extern "C" void kernel_launch(void* const* d_in, const int* in_sizes, int n_in,
                              void* d_out, int out_size) {
    const int*   x          = (const int*)d_in[0];
    const int*   edge_index = (const int*)d_in[1];
    const int*   edge_attr  = (const int*)d_in[2];
    const int*   batch      = (const int*)d_in[3];
    const float* node_emb   = (const float*)d_in[4];
    const float* edge_emb   = (const float*)d_in[5];
    const float* pre_lin_W  = (const float*)d_in[6];
    const float* pre_lin_b  = (const float*)d_in[7];
    const float* edge_enc_W = (const float*)d_in[8];
    const float* edge_enc_b = (const float*)d_in[9];
    const float* pre_W      = (const float*)d_in[10];
    const float* pre_b      = (const float*)d_in[11];
    const float* post_W     = (const float*)d_in[12];
    const float* post_b     = (const float*)d_in[13];
    const float* lin_W      = (const float*)d_in[14];
    const float* lin_b      = (const float*)d_in[15];
    const float* bn_g       = (const float*)d_in[16];
    const float* bn_b       = (const float*)d_in[17];
    const float* mlp_W1     = (const float*)d_in[18];
    const float* mlp_b1     = (const float*)d_in[19];
    const float* mlp_W2     = (const float*)d_in[20];
    const float* mlp_b2     = (const float*)d_in[21];
    const float* mlp_W3     = (const float*)d_in[22];
    const float* mlp_b3     = (const float*)d_in[23];
    float* out = (float*)d_out;

    // prologue: 5 launches
    k_prep1<<<(PREP1_TOTAL + 255) / 256, 256>>>(x, node_emb, pre_lin_W, pre_lin_b,
                                                pre_W, edge_emb, edge_enc_W, edge_enc_b,
                                                post_W, lin_W, post_b, lin_b);
    k_prep2<<<(N_EDGES + N_LAYERS * 16 * P3STRIDE + N_NODES + 255) / 256, 256>>>(edge_index, batch);
    k_scan<<<1, 1024>>>();
    k_fill<<<(N_EDGES + 255) / 256, 256>>>(edge_index, edge_attr);
    k_gemm_p<<<dim3(6, (N_NODES + 127) / 128), 256>>>(0, pre_b);

    for (int l = 0; l < N_LAYERS; l++) {
        if (l > 0) {
            k_gemm_p<<<dim3(6, (N_NODES + 127) / 128), 256>>>(l, pre_b);
        }
        k_agg_fused<<<N_NODES, 192>>>(l);
        k_gemm_hc<<<dim3(2, (N_NODES + 63) / 64, 2), 256>>>(l);
        k_combine<<<N_NODES / 25, 256>>>(l, bn_g, bn_b);
    }

    k_pool<<<N_GRAPHS, 128>>>();
    k_mlp<<<N_GRAPHS, 128>>>(mlp_W1, mlp_b1, mlp_W2, mlp_b2, mlp_W3, mlp_b3, out);
}

// round 16
// speedup vs baseline: 1.0432x; 1.0052x over previous
#include <cuda_runtime.h>
#include <math.h>
#include <stdint.h>

#define N_NODES 10000
#define N_EDGES 160000
#define N_GRAPHS 64
#define T_TOW 5
#define FI 75
#define FO 15
#define N_LAYERS 4
#define MSG_DIM 375        // T*FI
#define MIN_DIM 225
#define OUT_DIM 975
#define POST_DIM 75
#define PSTRIDE 752        // padded P row: [P1 0..374 | pad | P2 376..750 | pad]
#define P3STRIDE 376
#define HCK 1600
#define HCK2 800
#define HCN 225
#define AVG_DEG_LOG 2.8332133440562162f

// prep1 region sizes
#define NT   (N_LAYERS * MIN_DIM * MSG_DIM)
#define NE   (N_LAYERS * 16 * FI)
#define NB2  (N_LAYERS * FI)
#define NBZ  (N_LAYERS * FI)
#define NPZ  (N_GRAPHS * FI)
#define NCZ  (N_NODES)
#define NH0  (N_NODES * FI)
#define NWB  (N_LAYERS * HCK * HCN)
#define PREP1_TOTAL (NT + NE + NB2 + NBZ + NPZ + NCZ + NH0 + NWB)

// ---------------- scratch (device-side access only) -----------------------------
__device__ float d_h[N_NODES * FI];
__device__ float d_hc[N_NODES * FI];
__device__ float d_P[N_NODES * PSTRIDE];           // pads stay 0
__device__ float d_agg[N_NODES * 1500];
__device__ float d_G0[N_NODES * HCN];
__device__ float d_G1[N_NODES * HCN];
__device__ float d_Wt[N_LAYERS * MIN_DIM * MSG_DIM];
__device__ float d_WB2[N_LAYERS * HCK * HCN];
__device__ float d_P3[N_LAYERS * 16 * P3STRIDE];
__device__ float d_enctab[N_LAYERS * 16 * FI];
__device__ float d_bias2[N_LAYERS * FI];
__device__ int   d_cnt[N_NODES];
__device__ int   d_rowstart[N_NODES + 1];
__device__ int   d_cursor[N_NODES];
__device__ int   d_sc_csr[N_EDGES];                // src*16 + combo
__device__ int   d_gstart[N_GRAPHS + 1];
__device__ float d_bnsum[N_LAYERS * FI];
__device__ float d_bnsq[N_LAYERS * FI];
__device__ float d_bnscale[N_LAYERS * FI];
__device__ float d_bnshift[N_LAYERS * FI];
__device__ float d_pool[N_GRAPHS * FI];
__device__ int   d_combine_cnt;

__device__ __forceinline__ float tf32r(float v) {
    uint32_t o;
    asm("cvt.rna.tf32.f32 %0, %1;" : "=r"(o) : "f"(v));
    return __uint_as_float(o);
}

__device__ __forceinline__ void mma_tf32(float* c, const uint32_t* a, const uint32_t* b) {
    asm volatile(
        "mma.sync.aligned.m16n8k8.row.col.f32.tf32.tf32.f32 "
        "{%0,%1,%2,%3}, {%4,%5,%6,%7}, {%8,%9}, {%0,%1,%2,%3};"
        : "+f"(c[0]), "+f"(c[1]), "+f"(c[2]), "+f"(c[3])
        : "r"(a[0]), "r"(a[1]), "r"(a[2]), "r"(a[3]), "r"(b[0]), "r"(b[1]));
}

__device__ __forceinline__ float hval(int l, int n, int f) {
    if (l == 0) return d_h[n * FI + f];
    int o = (l - 1) * FI + f;
    return fmaxf(d_hc[n * FI + f] * d_bnscale[o] + d_bnshift[o], 0.f);
}

// ---------------- prep1: all independent prologue work in one launch ----------------
__global__ void k_prep1(const int* __restrict__ x, const float* __restrict__ node_emb,
                        const float* __restrict__ pre_lin_W, const float* __restrict__ pre_lin_b,
                        const float* __restrict__ preW,
                        const float* __restrict__ edge_emb,
                        const float* __restrict__ encW, const float* __restrict__ encb,
                        const float* __restrict__ postW, const float* __restrict__ linW,
                        const float* __restrict__ postb, const float* __restrict__ linb) {
    int idx = blockIdx.x * blockDim.x + threadIdx.x;
    if (idx < NT) {
        int l = idx / (MIN_DIM * MSG_DIM);
        int r = idx % (MIN_DIM * MSG_DIM);
        int c = r / MSG_DIM, j = r % MSG_DIM;
        int t = j / FI, f = j % FI;
        d_Wt[idx] = preW[((size_t)l * T_TOW + t) * MIN_DIM * FI + c * FI + f];
        return;
    }
    idx -= NT;
    if (idx < NE) {
        int l = idx / (16 * FI);
        int r = idx % (16 * FI);
        int combo = r / FI, f = r % FI;
        int a0 = combo >> 2, a1 = combo & 3;
        const float* e0 = edge_emb + a0 * 25;
        const float* e1 = edge_emb + a1 * 25;
        const float* W = encW + l * 50 * FI;
        float acc = encb[l * FI + f];
        #pragma unroll 5
        for (int q = 0; q < 25; q++) acc += e0[q] * W[q * FI + f];
        #pragma unroll 5
        for (int q = 0; q < 25; q++) acc += e1[q] * W[(25 + q) * FI + f];
        d_enctab[idx] = acc;
        return;
    }
    idx -= NE;
    if (idx < NB2) {
        int l = idx / FI, j = idx % FI;
        const float* lW = linW + l * POST_DIM * FI;
        float acc = linb[l * FI + j];
        #pragma unroll 5
        for (int q = 0; q < POST_DIM; q++) acc += postb[l * POST_DIM + q] * lW[q * FI + j];
        d_bias2[idx] = acc;
        return;
    }
    idx -= NB2;
    if (idx < NBZ) { d_bnsum[idx] = 0.f; d_bnsq[idx] = 0.f; return; }
    idx -= NBZ;
    if (idx < NPZ) { d_pool[idx] = 0.f; return; }
    idx -= NPZ;
    if (idx < NCZ) {
        d_cnt[idx] = 0;
        if (idx == 0) d_combine_cnt = 0;
        return;
    }
    idx -= NCZ;
    if (idx < NH0) {
        int n = idx / FI, f = idx % FI;
        int i0 = x[n * 2 + 0], i1 = x[n * 2 + 1];
        const float* e0 = node_emb + i0 * FI;
        const float* e1 = node_emb + i1 * FI;
        float acc = pre_lin_b[f];
        #pragma unroll 5
        for (int c = 0; c < FI; c++) acc += e0[c] * pre_lin_W[c * FI + f];
        #pragma unroll 5
        for (int c = 0; c < FI; c++) acc += e1[c] * pre_lin_W[(FI + c) * FI + f];
        d_h[idx] = acc;
        return;
    }
    idx -= NH0;
    if (idx < NWB) {
        int l = idx / (HCK * HCN);
        int r = idx % (HCK * HCN);
        int k = r / HCN, j = r % HCN;
        const float* pW = postW + (size_t)l * T_TOW * OUT_DIM * FO;
        const float* lW = linW + l * POST_DIM * FI;
        float acc = 0.f;
        if (k < 1500) {
            int t = k / 300, k300 = k % 300;
            int sel = j / FI, jj = j % FI;
            int c = FI + sel * 300 + k300;
            const float* pw = pW + ((size_t)t * OUT_DIM + c) * FO;
            const float* lw = lW + (t * FO) * FI + jj;
            #pragma unroll
            for (int f = 0; f < FO; f++) acc += pw[f] * lw[f * FI];
        } else if (k < 1575 && j < FI) {
            int c = k - 1500;
            #pragma unroll
            for (int t = 0; t < T_TOW; t++) {
                const float* pw = pW + ((size_t)t * OUT_DIM + c) * FO;
                const float* lw = lW + (t * FO) * FI + j;
                #pragma unroll
                for (int f = 0; f < FO; f++) acc += pw[f] * lw[f * FI];
            }
        }
        d_WB2[idx] = acc;
    }
}

// ---------------- prep2: count + P3 + graph segment starts --------------------------
__global__ void k_prep2(const int* __restrict__ edge_index, const int* __restrict__ batch) {
    int idx = blockIdx.x * blockDim.x + threadIdx.x;
    if (idx < N_EDGES) {
        atomicAdd(&d_cnt[edge_index[N_EDGES + idx]], 1);
        return;
    }
    idx -= N_EDGES;
    if (idx < N_LAYERS * 16 * P3STRIDE) {
        int l = idx / (16 * P3STRIDE);
        int r = idx % (16 * P3STRIDE);
        int combo = r / P3STRIDE, j = r % P3STRIDE;
        float acc = 0.f;
        if (j < MSG_DIM) {
            const float* e = d_enctab + (l * 16 + combo) * FI;
            const float* W = d_Wt + (size_t)l * MIN_DIM * MSG_DIM;
            #pragma unroll 5
            for (int k = 0; k < FI; k++) acc += e[k] * W[(2 * FI + k) * MSG_DIM + j];
        }
        d_P3[idx] = acc;
        return;
    }
    idx -= N_LAYERS * 16 * P3STRIDE;
    if (idx < N_NODES) {
        int n = idx;
        int b = batch[n];
        int pb = (n > 0) ? batch[n - 1] : -1;
        for (int g = pb + 1; g <= b; g++) d_gstart[g] = n;
        if (n == N_NODES - 1) {
            for (int g = b + 1; g <= N_GRAPHS; g++) d_gstart[g] = N_NODES;
        }
    }
}

// ---------------- scan + fill ---------------------------------------------------------
__global__ void k_scan() {
    __shared__ int ssum[1024];
    int tid = threadIdx.x;
    const int ITEMS = 10;
    int base = tid * ITEMS;
    int local[ITEMS];
    int s = 0;
    #pragma unroll
    for (int i = 0; i < ITEMS; i++) {
        int g = base + i;
        int v = (g < N_NODES) ? d_cnt[g] : 0;
        local[i] = s;
        s += v;
    }
    ssum[tid] = s;
    __syncthreads();
    for (int off = 1; off < 1024; off <<= 1) {
        int v = (tid >= off) ? ssum[tid - off] : 0;
        __syncthreads();
        ssum[tid] += v;
        __syncthreads();
    }
    int excl = (tid == 0) ? 0 : ssum[tid - 1];
    #pragma unroll
    for (int i = 0; i < ITEMS; i++) {
        int g = base + i;
        if (g < N_NODES) {
            int rs = excl + local[i];
            d_rowstart[g] = rs;
            d_cursor[g]   = rs;
        }
    }
    if (tid == 0) d_rowstart[N_NODES] = ssum[1023];
}

__global__ void k_fill(const int* __restrict__ edge_index, const int* __restrict__ edge_attr) {
    int e = blockIdx.x * blockDim.x + threadIdx.x;
    if (e >= N_EDGES) return;
    int dst = edge_index[N_EDGES + e];
    int pos = atomicAdd(&d_cursor[dst], 1);
    d_sc_csr[pos] = edge_index[e] * 16 + edge_attr[e * 2] * 4 + edge_attr[e * 2 + 1];
}

// ---------------- P GEMM (BM=128): P[n] = [h|h] @ [W1|W2] + [bias|0] ------------------
__global__ void __launch_bounds__(256, 2) k_gemm_p(int l, const float* __restrict__ bias_all) {
    const int AS = 84, BS = 136;
    __shared__ float As[128 * AS];
    __shared__ float Bs[80 * BS];
    const float* Wt = d_Wt + (size_t)l * MIN_DIM * MSG_DIM;
    const float* bias = bias_all + l * MSG_DIM;
    int tid = threadIdx.x;
    int row0 = blockIdx.y * 128;
    int col0 = blockIdx.x * 128;
    int lane = tid & 31, warp = tid >> 5;
    int wm = (warp >> 2) * 64, wn = (warp & 3) * 32;
    int g = lane >> 2, tc = lane & 3;

    #pragma unroll
    for (int i = 0; i < 40; i++) {
        int idx = i * 256 + tid;
        int r = idx / 80, c = idx - r * 80;
        int grow = row0 + r;
        float v = (grow < N_NODES && c < FI) ? hval(l, grow, c) : 0.f;
        As[r * AS + c] = tf32r(v);
    }
    #pragma unroll
    for (int i = 0; i < 40; i++) {
        int idx = i * 256 + tid;
        int kr = idx >> 7, c = idx & 127;
        int j = col0 + c;
        float v = 0.f;
        if (kr < FI && j < 750)
            v = (j < MSG_DIM) ? Wt[kr * MSG_DIM + j] : Wt[(FI + kr) * MSG_DIM + (j - MSG_DIM)];
        Bs[kr * BS + c] = tf32r(v);
    }
    __syncthreads();

    float acc[4][4][4];
    #pragma unroll
    for (int i = 0; i < 4; i++)
        #pragma unroll
        for (int j = 0; j < 4; j++)
            #pragma unroll
            for (int q = 0; q < 4; q++) acc[i][j][q] = 0.f;

    #pragma unroll
    for (int kk = 0; kk < 80; kk += 8) {
        uint32_t a[4][4], b[4][2];
        #pragma unroll
        for (int i = 0; i < 4; i++) {
            int m = wm + i * 16 + g;
            a[i][0] = __float_as_uint(As[m * AS + kk + tc]);
            a[i][1] = __float_as_uint(As[(m + 8) * AS + kk + tc]);
            a[i][2] = __float_as_uint(As[m * AS + kk + tc + 4]);
            a[i][3] = __float_as_uint(As[(m + 8) * AS + kk + tc + 4]);
        }
        #pragma unroll
        for (int j = 0; j < 4; j++) {
            int n = wn + j * 8 + g;
            b[j][0] = __float_as_uint(Bs[(kk + tc) * BS + n]);
            b[j][1] = __float_as_uint(Bs[(kk + tc + 4) * BS + n]);
        }
        #pragma unroll
        for (int i = 0; i < 4; i++)
            #pragma unroll
            for (int j = 0; j < 4; j++) mma_tf32(acc[i][j], a[i], b[j]);
    }

    #pragma unroll
    for (int i = 0; i < 4; i++) {
        int r = row0 + wm + i * 16 + g;
        #pragma unroll
        for (int j = 0; j < 4; j++) {
            int cb = col0 + wn + j * 8 + 2 * tc;
            if (cb < 750) {
                int o0 = (cb < MSG_DIM) ? cb : cb + 1;
                float b0 = (cb < MSG_DIM) ? bias[cb] : 0.f;
                if (r < N_NODES) d_P[(size_t)r * PSTRIDE + o0] = acc[i][j][0] + b0;
                if (r + 8 < N_NODES) d_P[(size_t)(r + 8) * PSTRIDE + o0] = acc[i][j][2] + b0;
                if (cb + 1 < 750) {
                    int o1 = (cb + 1 < MSG_DIM) ? cb + 1 : cb + 2;
                    float b1 = (cb + 1 < MSG_DIM) ? bias[cb + 1] : 0.f;
                    if (r < N_NODES) d_P[(size_t)r * PSTRIDE + o1] = acc[i][j][1] + b1;
                    if (r + 8 < N_NODES) d_P[(size_t)(r + 8) * PSTRIDE + o1] = acc[i][j][3] + b1;
                }
            }
        }
    }
}

// ---------------- fused message + aggregation (float2, 192t, 2-edge unroll) -----------
__global__ void k_agg_fused(int l) {
    int n = blockIdx.x;
    int t = threadIdx.x;            // 192 threads, 188 active (2 cols each)
    if (t >= 188) return;
    int j = 2 * t;
    const float2* P3 = (const float2*)(d_P3 + (size_t)l * 16 * P3STRIDE);
    int s0 = d_rowstart[n], s1 = d_rowstart[n + 1];
    float2 p1 = *(const float2*)(d_P + (size_t)n * PSTRIDE + j);
    float sx = 0.f, sy = 0.f, qx = 0.f, qy = 0.f;
    float mnx = 3.4e38f, mny = 3.4e38f, mxx = -3.4e38f, mxy = -3.4e38f;
    int i = s0;
    for (; i + 1 < s1; i += 2) {
        int sc0 = d_sc_csr[i];
        int sc1 = d_sc_csr[i + 1];
        float2 a0 = *(const float2*)(d_P + (size_t)(sc0 >> 4) * PSTRIDE + 376 + j);
        float2 a1 = *(const float2*)(d_P + (size_t)(sc1 >> 4) * PSTRIDE + 376 + j);
        float2 b0 = P3[(sc0 & 15) * 188 + t];
        float2 b1 = P3[(sc1 & 15) * 188 + t];
        float v0x = p1.x + a0.x + b0.x;
        float v0y = p1.y + a0.y + b0.y;
        float v1x = p1.x + a1.x + b1.x;
        float v1y = p1.y + a1.y + b1.y;
        sx += v0x; sy += v0y;
        qx += v0x * v0x; qy += v0y * v0y;
        mnx = fminf(mnx, v0x); mny = fminf(mny, v0y);
        mxx = fmaxf(mxx, v0x); mxy = fmaxf(mxy, v0y);
        sx += v1x; sy += v1y;
        qx += v1x * v1x; qy += v1y * v1y;
        mnx = fminf(mnx, v1x); mny = fminf(mny, v1y);
        mxx = fmaxf(mxx, v1x); mxy = fmaxf(mxy, v1y);
    }
    if (i < s1) {
        int sc0 = d_sc_csr[i];
        float2 a0 = *(const float2*)(d_P + (size_t)(sc0 >> 4) * PSTRIDE + 376 + j);
        float2 b0 = P3[(sc0 & 15) * 188 + t];
        float v0x = p1.x + a0.x + b0.x;
        float v0y = p1.y + a0.y + b0.y;
        sx += v0x; sy += v0y;
        qx += v0x * v0x; qy += v0y * v0y;
        mnx = fminf(mnx, v0x); mny = fminf(mny, v0y);
        mxx = fmaxf(mxx, v0x); mxy = fmaxf(mxy, v0y);
    }
    float cnt = (float)(s1 - s0);
    float deg = fmaxf(cnt, 1.f);
    bool empty = (s1 == s0);
    float* abase = d_agg + (size_t)n * 1500;
    #pragma unroll
    for (int k = 0; k < 2; k++) {
        int jj = j + k;
        if (jj >= MSG_DIM) break;
        float s = k ? sy : sx;
        float q = k ? qy : qx;
        float mn = k ? mny : mnx;
        float mx = k ? mxy : mxx;
        float mean = s / deg;
        float var = q / deg - mean * mean;
        if (var < 0.f) var = 0.f;
        float stdv = sqrtf(var + 1e-5f);
        if (empty) { mn = 0.f; mx = 0.f; }
        int tw = jj / FI, f = jj % FI;
        float* a = abase + tw * (4 * FI);
        a[f]          = mean;
        a[FI + f]     = mn;
        a[2 * FI + f] = mx;
        a[3 * FI + f] = stdv;
    }
}

// ---------------- hc GEMM (split-K=2), BN fused on K-tail -----------------------------
__global__ void __launch_bounds__(256, 2) k_gemm_hc(int l) {
    const int AS = 84, BS = 136;
    __shared__ float As[64 * AS];
    __shared__ float Bs[80 * BS];
    const float* WB2 = d_WB2 + (size_t)l * HCK * HCN;
    int tid = threadIdx.x;
    int row0 = blockIdx.y * 64;
    int col0 = blockIdx.x * 128;
    int z = blockIdx.z;
    int lane = tid & 31, warp = tid >> 5;
    int wm = (warp >> 2) * 32, wn = (warp & 3) * 32;
    int g = lane >> 2, tc = lane & 3;

    float acc[2][4][4];
    #pragma unroll
    for (int i = 0; i < 2; i++)
        #pragma unroll
        for (int j = 0; j < 4; j++)
            #pragma unroll
            for (int q = 0; q < 4; q++) acc[i][j][q] = 0.f;

    int kbeg = z * HCK2, kend = kbeg + HCK2;
    for (int k0 = kbeg; k0 < kend; k0 += 80) {
        #pragma unroll
        for (int i = 0; i < 20; i++) {
            int idx = i * 256 + tid;
            int r = idx / 80, c = idx - r * 80;
            int grow = row0 + r;
            int gc = k0 + c;
            float v = 0.f;
            if (grow < N_NODES) {
                if (gc < 1500) v = d_agg[(size_t)grow * 1500 + gc];
                else if (gc < 1575) v = hval(l, grow, gc - 1500);
            }
            As[r * AS + c] = tf32r(v);
        }
        #pragma unroll
        for (int i = 0; i < 40; i++) {
            int idx = i * 256 + tid;
            int kr = idx >> 7, c = idx & 127;
            int j = col0 + c;
            float v = (j < HCN) ? WB2[(size_t)(k0 + kr) * HCN + j] : 0.f;
            Bs[kr * BS + c] = tf32r(v);
        }
        __syncthreads();
        #pragma unroll
        for (int kk = 0; kk < 80; kk += 8) {
            uint32_t a[2][4], b[4][2];
            #pragma unroll
            for (int i = 0; i < 2; i++) {
                int m = wm + i * 16 + g;
                a[i][0] = __float_as_uint(As[m * AS + kk + tc]);
                a[i][1] = __float_as_uint(As[(m + 8) * AS + kk + tc]);
                a[i][2] = __float_as_uint(As[m * AS + kk + tc + 4]);
                a[i][3] = __float_as_uint(As[(m + 8) * AS + kk + tc + 4]);
            }
            #pragma unroll
            for (int j = 0; j < 4; j++) {
                int n = wn + j * 8 + g;
                b[j][0] = __float_as_uint(Bs[(kk + tc) * BS + n]);
                b[j][1] = __float_as_uint(Bs[(kk + tc + 4) * BS + n]);
            }
            #pragma unroll
            for (int i = 0; i < 2; i++)
                #pragma unroll
                for (int j = 0; j < 4; j++) mma_tf32(acc[i][j], a[i], b[j]);
        }
        __syncthreads();
    }

    float* gout = (z == 0) ? d_G0 : d_G1;
    #pragma unroll
    for (int i = 0; i < 2; i++) {
        int r = row0 + wm + i * 16 + g;
        #pragma unroll
        for (int j = 0; j < 4; j++) {
            int cb = col0 + wn + j * 8 + 2 * tc;
            if (cb < HCN) {
                if (r < N_NODES) {
                    gout[(size_t)r * HCN + cb] = acc[i][j][0];
                    if (cb + 1 < HCN) gout[(size_t)r * HCN + cb + 1] = acc[i][j][1];
                }
                if (r + 8 < N_NODES) {
                    gout[(size_t)(r + 8) * HCN + cb] = acc[i][j][2];
                    if (cb + 1 < HCN) gout[(size_t)(r + 8) * HCN + cb + 1] = acc[i][j][3];
                }
            }
        }
    }
}

// ---------------- combine G0+G1 -> hc + BN stats + fused bnfin (last block) ------------
__global__ void k_combine(int l, const float* __restrict__ bn_g, const float* __restrict__ bn_b) {
    __shared__ float ssum[FI], ssq[FI];
    __shared__ bool isLast;
    int tid = threadIdx.x;
    if (tid < FI) { ssum[tid] = 0.f; ssq[tid] = 0.f; }
    __syncthreads();
    const float* bias2 = d_bias2 + l * FI;
    int base = blockIdx.x * 25;
    for (int idx = tid; idx < 25 * FI; idx += blockDim.x) {
        int n = base + idx / FI, f = idx % FI;
        float cnt = (float)(d_rowstart[n + 1] - d_rowstart[n]);
        float log_deg = logf(fmaxf(cnt, 1.f) + 1.f);
        float amp = log_deg / AVG_DEG_LOG;
        float att = AVG_DEG_LOG / log_deg;
        const float* g0 = d_G0 + (size_t)n * HCN;
        const float* g1 = d_G1 + (size_t)n * HCN;
        float v = (g0[f] + g1[f])
                + amp * (g0[FI + f] + g1[FI + f])
                + att * (g0[2 * FI + f] + g1[2 * FI + f]) + bias2[f];
        d_hc[n * FI + f] = v;
        atomicAdd(&ssum[f], v);
        atomicAdd(&ssq[f], v * v);
    }
    __syncthreads();
    if (tid < FI) {
        atomicAdd(&d_bnsum[l * FI + tid], ssum[tid]);
        atomicAdd(&d_bnsq[l * FI + tid], ssq[tid]);
    }
    __threadfence();
    __syncthreads();
    if (tid == 0) {
        int old = atomicAdd(&d_combine_cnt, 1);
        isLast = (old == gridDim.x - 1);
    }
    __syncthreads();
    if (isLast) {
        if (tid < FI) {
            float mu = d_bnsum[l * FI + tid] / (float)N_NODES;
            float var = d_bnsq[l * FI + tid] / (float)N_NODES - mu * mu;
            float sc = bn_g[l * FI + tid] * rsqrtf(var + 1e-5f);
            d_bnscale[l * FI + tid] = sc;
            d_bnshift[l * FI + tid] = bn_b[l * FI + tid] - mu * sc;
        }
        if (tid == 0) d_combine_cnt = 0;
    }
}

// ---------------- pool: per-graph segment reduce (BN fused, no atomics) ------------------
__global__ void k_pool() {
    int gi = blockIdx.x;
    int f = threadIdx.x;
    if (f >= FI) return;
    int n0 = d_gstart[gi], n1 = d_gstart[gi + 1];
    int o = (N_LAYERS - 1) * FI + f;
    float sc = d_bnscale[o], sh = d_bnshift[o];
    float acc = 0.f;
    for (int n = n0; n < n1; n++) {
        float v = d_hc[n * FI + f] * sc + sh;
        acc += fmaxf(v, 0.f);
    }
    d_pool[gi * FI + f] = acc;
}

__global__ void k_mlp(const float* __restrict__ W1, const float* __restrict__ b1,
                      const float* __restrict__ W2, const float* __restrict__ b2,
                      const float* __restrict__ W3, const float* __restrict__ b3,
                      float* __restrict__ out) {
    __shared__ float g[FI], h1[50], h2[25];
    int gi = blockIdx.x;
    int tid = threadIdx.x;
    if (tid < FI) g[tid] = d_pool[gi * FI + tid];
    __syncthreads();
    if (tid < 50) {
        float a = b1[tid];
        for (int c = 0; c < FI; c++) a += g[c] * W1[c * 50 + tid];
        h1[tid] = fmaxf(a, 0.f);
    }
    __syncthreads();
    if (tid < 25) {
        float a = b2[tid];
        for (int c = 0; c < 50; c++) a += h1[c] * W2[c * 25 + tid];
        h2[tid] = fmaxf(a, 0.f);
    }
    __syncthreads();
    if (tid == 0) {
        float a = b3[0];
        for (int c = 0; c < 25; c++) a += h2[c] * W3[c];
        out[gi] = a;
    }
}

// ---------------- launch --------------------------------------------------------------------
extern "C" void kernel_launch(void* const* d_in, const int* in_sizes, int n_in,
                              void* d_out, int out_size) {
    const int*   x          = (const int*)d_in[0];
    const int*   edge_index = (const int*)d_in[1];
    const int*   edge_attr  = (const int*)d_in[2];
    const int*   batch      = (const int*)d_in[3];
    const float* node_emb   = (const float*)d_in[4];
    const float* edge_emb   = (const float*)d_in[5];
    const float* pre_lin_W  = (const float*)d_in[6];
    const float* pre_lin_b  = (const float*)d_in[7];
    const float* edge_enc_W = (const float*)d_in[8];
    const float* edge_enc_b = (const float*)d_in[9];
    const float* pre_W      = (const float*)d_in[10];
    const float* pre_b      = (const float*)d_in[11];
    const float* post_W     = (const float*)d_in[12];
    const float* post_b     = (const float*)d_in[13];
    const float* lin_W      = (const float*)d_in[14];
    const float* lin_b      = (const float*)d_in[15];
    const float* bn_g       = (const float*)d_in[16];
    const float* bn_b       = (const float*)d_in[17];
    const float* mlp_W1     = (const float*)d_in[18];
    const float* mlp_b1     = (const float*)d_in[19];
    const float* mlp_W2     = (const float*)d_in[20];
    const float* mlp_b2     = (const float*)d_in[21];
    const float* mlp_W3     = (const float*)d_in[22];
    const float* mlp_b3     = (const float*)d_in[23];
    float* out = (float*)d_out;

    // prologue: 5 launches
    k_prep1<<<(PREP1_TOTAL + 255) / 256, 256>>>(x, node_emb, pre_lin_W, pre_lin_b,
                                                pre_W, edge_emb, edge_enc_W, edge_enc_b,
                                                post_W, lin_W, post_b, lin_b);
    k_prep2<<<(N_EDGES + N_LAYERS * 16 * P3STRIDE + N_NODES + 255) / 256, 256>>>(edge_index, batch);
    k_scan<<<1, 1024>>>();
    k_fill<<<(N_EDGES + 255) / 256, 256>>>(edge_index, edge_attr);
    k_gemm_p<<<dim3(6, (N_NODES + 127) / 128), 256>>>(0, pre_b);

    for (int l = 0; l < N_LAYERS; l++) {
        if (l > 0) {
            k_gemm_p<<<dim3(6, (N_NODES + 127) / 128), 256>>>(l, pre_b);
        }
        k_agg_fused<<<N_NODES, 192>>>(l);
        k_gemm_hc<<<dim3(2, (N_NODES + 63) / 64, 2), 256>>>(l);
        k_combine<<<N_NODES / 25, 256>>>(l, bn_g, bn_b);
    }

    k_pool<<<N_GRAPHS, 128>>>();
    k_mlp<<<N_GRAPHS, 128>>>(mlp_W1, mlp_b1, mlp_W2, mlp_b2, mlp_W3, mlp_b3, out);
}